// round 5
// baseline (speedup 1.0000x reference)
#include <cuda_runtime.h>
#include <math.h>
#include <stdint.h>

// ---------------- problem constants ----------------
#define Nn      32768
#define Ll      3000
#define PERG    64
#define NG      512          // Nn / PERG
#define DEGc    16
#define Ec      (Nn*DEGc)    // 524288
#define HIDc    128
#define OUT3c   64
#define REDc    146
#define FINc    4672         // 32*146
#define EPSf    1e-5f
#define NGRP    73           // p-groups of 2

// ---------------- device scratch (static, no allocs) ----------------
__device__ float g_deg[Nn];
__device__ float g_dinv[Nn];
__device__ float g_A[NG*64*64];                 // 8 MB
__device__ float g_h1[(size_t)Nn * HIDc];       // 16 MB
__device__ float g_h2[(size_t)Nn * HIDc];       // 16 MB
__device__ float g_W1r[(size_t)HIDc * FINc];    // 2.4 MB: W1 reordered k=p*32+c, [n][k], tf32
__device__ float g_Wc[32*108];                  // conv weights, tf32, pitch 108, zero pad

// ---------------- helpers ----------------
__device__ __forceinline__ float tf32r(float x) {
    uint32_t u;
    asm("cvt.rna.tf32.f32 %0, %1;" : "=r"(u) : "f"(x));
    return __uint_as_float(u);
}
__device__ __forceinline__ void mma_tf32(float* d, const uint32_t* a, uint32_t b0, uint32_t b1) {
    asm volatile(
        "mma.sync.aligned.m16n8k8.row.col.f32.tf32.tf32.f32 "
        "{%0,%1,%2,%3}, {%4,%5,%6,%7}, {%8,%9}, {%0,%1,%2,%3};"
        : "+f"(d[0]), "+f"(d[1]), "+f"(d[2]), "+f"(d[3])
        : "r"(a[0]), "r"(a[1]), "r"(a[2]), "r"(a[3]), "r"(b0), "r"(b1));
}
__device__ __forceinline__ uint32_t smem_u32(const void* p) {
    uint32_t a;
    asm("{ .reg .u64 t; cvta.to.shared.u64 t, %1; cvt.u32.u64 %0, t; }" : "=r"(a) : "l"(p));
    return a;
}
__device__ __forceinline__ void cp16(uint32_t dst, const void* src) {
    asm volatile("cp.async.cg.shared.global [%0], [%1], 16;" :: "r"(dst), "l"(src));
}
#define CP_COMMIT() asm volatile("cp.async.commit_group;" ::: "memory")
#define CP_WAIT2()  asm volatile("cp.async.wait_group 2;" ::: "memory")
#define CP_WAIT1()  asm volatile("cp.async.wait_group 1;" ::: "memory")
#define CP_WAIT0()  asm volatile("cp.async.wait_group 0;" ::: "memory")

// ---------------- degree / dinv ----------------
__global__ void k_deg_init() {
    int i = blockIdx.x * blockDim.x + threadIdx.x;
    if (i < Nn) g_deg[i] = 1.0f;
}
__global__ void k_deg_accum(const int* __restrict__ dst, const float* __restrict__ w) {
    int e = blockIdx.x * blockDim.x + threadIdx.x;
    if (e < Ec) atomicAdd(&g_deg[dst[e]], w[e]);
}
__global__ void k_dinv() {
    int i = blockIdx.x * blockDim.x + threadIdx.x;
    if (i < Nn) g_dinv[i] = rsqrtf(g_deg[i]);
}

// ---------------- per-graph aggregation matrix ----------------
__global__ void __launch_bounds__(256) k_buildA(const int* __restrict__ src,
                                                const int* __restrict__ dst,
                                                const float* __restrict__ w) {
    __shared__ float sA[64*64];
    __shared__ float sdin[64];
    const int g = blockIdx.x, tid = threadIdx.x;
    for (int i = tid; i < 4096; i += 256) sA[i] = 0.f;
    if (tid < 64) sdin[tid] = g_dinv[g*64 + tid];
    __syncthreads();
    const int base = g * (PERG * DEGc);
    for (int e = tid; e < PERG*DEGc; e += 256) {
        int s = src[base + e] - g*64;
        int d = dst[base + e] - g*64;
        float v = sdin[s] * w[base + e] * sdin[d];
        atomicAdd(&sA[d*64 + s], v);
    }
    __syncthreads();
    if (tid < 64) { float di = sdin[tid]; sA[tid*64 + tid] += di*di; }
    __syncthreads();
    for (int i = tid; i < 4096; i += 256) g_A[g*4096 + i] = sA[i];
}

// ---------------- W1 reorder: W1r[n][k=p*32+c] = tf32(W1[(c*146+p)*128 + n]) ----------------
__global__ void k_w1r(const float* __restrict__ W1) {
    int idx = blockIdx.x * blockDim.x + threadIdx.x;
    if (idx < HIDc * FINc) {
        int n = idx / FINc, k = idx % FINc;
        int p = k >> 5, c = k & 31;
        g_W1r[idx] = tf32r(W1[(size_t)(c*REDc + p)*HIDc + n]);
    }
}

// ---------------- conv weight prep: tf32, pitch 108, zero pad ----------------
__global__ void k_wc(const float* __restrict__ cw) {
    int i = blockIdx.x * blockDim.x + threadIdx.x;
    if (i < 32*108) {
        int c = i / 108, t = i % 108;
        g_Wc[i] = (t < 100) ? tf32r(cw[c*100 + t]) : 0.f;
    }
}

// ---------------- fused conv + GCN layer1, all tensor cores ----------------
// CTA = 1 graph (64 nodes), 256 threads (8 warps).
// Per p-group g (p = 2g, 2g+1):
//   MMA1: C[64 nodes][pl*32+ch] = Xwin @ Wc^T (implicit im2col, window offset 20*pl)
//   relu+bias+tf32 -> C staging
//   MMA2: Z[64][128] += C @ W1r[k=64g..64g+63]
// Epilogue: Y = A_g @ Z, bias+BN+relu -> g_h1.
// smem (floats): X0 [0,8448) X1 [8448,16896) pitch 132 | Wc [16896,20352) pitch 108
//                W1s [20352,29056) pitch 68 | Cs [29056,33408) pitch 68
__global__ void __launch_bounds__(256, 1) k_fused1(
    const float* __restrict__ x,  const float* __restrict__ cb,
    const float* __restrict__ bias,
    const float* __restrict__ gam, const float* __restrict__ bet,
    const float* __restrict__ mean, const float* __restrict__ var)
{
    extern __shared__ float smf[];
    const uint32_t sb = smem_u32(smf);
    const int tid  = threadIdx.x;
    const int g    = blockIdx.x;                 // graph
    const int warp = tid >> 5, lane = tid & 31;
    const int gID  = lane >> 2, tig = lane & 3;

    float* Wcs = smf + 16896;
    float* W1s = smf + 20352;
    float* Cs  = smf + 29056;

    // load conv weights once
    {
        const float4* w4 = reinterpret_cast<const float4*>(g_Wc);
        float4* d4 = reinterpret_cast<float4*>(Wcs);
        for (int i = tid; i < 864; i += 256) d4[i] = w4[i];
    }
    // conv bias regs: channel = nt*8 + 2*tig (+1)
    float bcv[4][2];
#pragma unroll
    for (int nt = 0; nt < 4; nt++) {
        bcv[nt][0] = cb[nt*8 + 2*tig];
        bcv[nt][1] = cb[nt*8 + 2*tig + 1];
    }

    const float* xg = x + (size_t)g * 64 * Ll;

    // X window load: 64 rows x 124 floats (31 cp16/row), group grp
    auto issueX = [&](int grp) {
        const uint32_t xb = sb + (uint32_t)((grp & 1) * 8448) * 4u;
        const int maxc4 = (grp == NGRP-1) ? 30 : 31;   // last group: 120 floats only
        for (int idx = tid; idx < 2048; idx += 256) {
            int row = idx >> 5, c4 = idx & 31;
            if (c4 < maxc4)
                cp16(xb + (uint32_t)(row*132 + c4*4)*4u,
                     xg + (size_t)row * Ll + 40*grp + c4*4);
        }
    };
    // W1r slice load: 128 n-rows x 64 k (16 cp16/row)
    auto issueW = [&](int grp) {
        const uint32_t wb = sb + 20352u*4u;
        for (int idx = tid; idx < 2048; idx += 256) {
            int n = idx >> 4, c4 = idx & 15;
            cp16(wb + (uint32_t)(n*68 + c4*4)*4u,
                 g_W1r + (size_t)n * FINc + 64*grp + c4*4);
        }
    };

    // MMA2 accumulators: warp grid 2x4 (wm rows 32, wn cols 32)
    const int wm = warp >> 2, wn = warp & 3;
    float accZ[2][4][4];
#pragma unroll
    for (int mi = 0; mi < 2; mi++)
#pragma unroll
        for (int j = 0; j < 4; j++)
#pragma unroll
            for (int c = 0; c < 4; c++) accZ[mi][j][c] = 0.f;

    // MMA1 warp roles: mt = warp&3 (m16 tile), pl = warp>>2
    const int mt = warp & 3, pl = warp >> 2;

    issueX(0); CP_COMMIT();

    for (int grp = 0; grp < NGRP; grp++) {
        issueW(grp); CP_COMMIT();
        if (grp + 1 < NGRP) issueX(grp + 1);
        CP_COMMIT();

        CP_WAIT2();            // X(grp) ready
        __syncthreads();

        // ---- MMA1: conv for this warp's (mt, pl) ----
        const float* Xs = smf + (grp & 1) * 8448;
        float accC[4][4];
#pragma unroll
        for (int nt = 0; nt < 4; nt++)
#pragma unroll
            for (int c = 0; c < 4; c++) accC[nt][c] = 0.f;
#pragma unroll
        for (int k8 = 0; k8 < 13; k8++) {
            const int k0 = k8 * 8;
            const int off = 20*pl + k0 + tig;
            uint32_t a[4];
            a[0] = __float_as_uint(Xs[(mt*16 + gID    )*132 + off]);
            a[1] = __float_as_uint(Xs[(mt*16 + gID + 8)*132 + off]);
            a[2] = __float_as_uint(Xs[(mt*16 + gID    )*132 + off + 4]);
            a[3] = __float_as_uint(Xs[(mt*16 + gID + 8)*132 + off + 4]);
#pragma unroll
            for (int nt = 0; nt < 4; nt++) {
                uint32_t b0 = __float_as_uint(Wcs[(nt*8 + gID)*108 + k0 + tig]);
                uint32_t b1 = __float_as_uint(Wcs[(nt*8 + gID)*108 + k0 + tig + 4]);
                mma_tf32(accC[nt], a, b0, b1);
            }
        }
        // ---- stage C: relu + bias + tf32, cols pl*32 + nt*8 + 2tig ----
#pragma unroll
        for (int nt = 0; nt < 4; nt++) {
            const int col = pl*32 + nt*8 + 2*tig;
            float v0 = tf32r(fmaxf(accC[nt][0] + bcv[nt][0], 0.f));
            float v1 = tf32r(fmaxf(accC[nt][1] + bcv[nt][1], 0.f));
            float v2 = tf32r(fmaxf(accC[nt][2] + bcv[nt][0], 0.f));
            float v3 = tf32r(fmaxf(accC[nt][3] + bcv[nt][1], 0.f));
            *reinterpret_cast<float2*>(Cs + (mt*16 + gID    )*68 + col) = make_float2(v0, v1);
            *reinterpret_cast<float2*>(Cs + (mt*16 + gID + 8)*68 + col) = make_float2(v2, v3);
        }

        CP_WAIT1();            // W1r(grp) ready (X(grp+1) may still fly)
        __syncthreads();

        // ---- MMA2: Z += C @ W1slice (K=64) ----
#pragma unroll
        for (int k8 = 0; k8 < 8; k8++) {
            const int k0 = k8 * 8;
            uint32_t a[2][4];
#pragma unroll
            for (int mi = 0; mi < 2; mi++) {
                int row = wm*32 + mi*16 + gID;
                a[mi][0] = __float_as_uint(Cs[row*68       + k0 + tig]);
                a[mi][1] = __float_as_uint(Cs[(row+8)*68   + k0 + tig]);
                a[mi][2] = __float_as_uint(Cs[row*68       + k0 + tig + 4]);
                a[mi][3] = __float_as_uint(Cs[(row+8)*68   + k0 + tig + 4]);
            }
#pragma unroll
            for (int j = 0; j < 4; j++) {
                int n = wn*32 + j*8 + gID;
                uint32_t b0 = __float_as_uint(W1s[n*68 + k0 + tig]);
                uint32_t b1 = __float_as_uint(W1s[n*68 + k0 + tig + 4]);
                mma_tf32(accZ[0][j], a[0], b0, b1);
                mma_tf32(accZ[1][j], a[1], b0, b1);
            }
        }
        __syncthreads();       // protect Cs/W1s before next iter's writes
    }

    CP_WAIT0();
    __syncthreads();

    // ---- stage Z (64 x 128, pitch 132) and A_g ----
    float* Zs = smf;                     // 64*132 = 8448 floats
    float* Ag = smf + 8448;              // 64*65
#pragma unroll
    for (int mi = 0; mi < 2; mi++)
#pragma unroll
        for (int j = 0; j < 4; j++) {
            int row = wm*32 + mi*16 + gID;
            int col = wn*32 + j*8 + 2*tig;
            *reinterpret_cast<float2*>(Zs + row*132 + col) =
                make_float2(accZ[mi][j][0], accZ[mi][j][1]);
            *reinterpret_cast<float2*>(Zs + (row+8)*132 + col) =
                make_float2(accZ[mi][j][2], accZ[mi][j][3]);
        }
    {
        const float* gA = g_A + (size_t)g * 4096;
        for (int i = tid; i < 4096; i += 256)
            Ag[(i >> 6)*65 + (i & 63)] = gA[i];
    }
    __syncthreads();

    // ---- Y = A_g @ Z, bias+BN+relu -> g_h1 ----
    {
        const int ty = tid >> 5;         // 0..7 -> rows ty*8..+7
        const int tx = tid & 31;         // cols tx*4..+3
        float ac[8][4];
#pragma unroll
        for (int r = 0; r < 8; r++)
#pragma unroll
            for (int j = 0; j < 4; j++) ac[r][j] = 0.f;
#pragma unroll 4
        for (int k = 0; k < 64; k++) {
            float a[8];
#pragma unroll
            for (int r = 0; r < 8; r++) a[r] = Ag[(ty*8 + r)*65 + k];
            float4 z4 = *reinterpret_cast<const float4*>(Zs + k*132 + tx*4);
            float z[4] = {z4.x, z4.y, z4.z, z4.w};
#pragma unroll
            for (int r = 0; r < 8; r++)
#pragma unroll
                for (int j = 0; j < 4; j++)
                    ac[r][j] = fmaf(a[r], z[j], ac[r][j]);
        }
        float sc[4], sh[4];
#pragma unroll
        for (int j = 0; j < 4; j++) {
            int col = tx*4 + j;
            float s = gam[col] * rsqrtf(var[col] + EPSf);
            sc[j] = s;
            sh[j] = (bias[col] - mean[col]) * s + bet[col];
        }
#pragma unroll
        for (int r = 0; r < 8; r++) {
            float v[4];
#pragma unroll
            for (int j = 0; j < 4; j++)
                v[j] = fmaxf(fmaf(ac[r][j], sc[j], sh[j]), 0.f);
            *reinterpret_cast<float4*>(g_h1 + (size_t)(g*64 + ty*8 + r)*HIDc + tx*4) =
                make_float4(v[0], v[1], v[2], v[3]);
        }
    }
}

// ---------------- fused GCN layer (fp32, layers 2 & 3) ----------------
template<int K, int COUT, bool FINAL>
__global__ void __launch_bounds__(256) k_layer(
    const float* __restrict__ Hin, const float* __restrict__ W,
    const float* __restrict__ bias,
    const float* __restrict__ gam, const float* __restrict__ bet,
    const float* __restrict__ mean, const float* __restrict__ var,
    float* __restrict__ Hout,
    const float* __restrict__ fcw, const float* __restrict__ fcb,
    float* __restrict__ out)
{
    extern __shared__ float sm[];
    constexpr int TN = COUT / 16;
    constexpr int AP = 36;
    constexpr int BP = COUT + 4;
    float* As = sm;
    float* Bs = sm + 64*AP;

    const int tid = threadIdx.x;
    const int tx  = tid & 15;
    const int ty  = tid >> 4;
    const int g   = blockIdx.x;

    float acc[4][TN];
#pragma unroll
    for (int r = 0; r < 4; r++)
#pragma unroll
        for (int j = 0; j < TN; j++) acc[r][j] = 0.f;

    const float* Hg = Hin + (size_t)g * 64 * K;
    const int lr = tid >> 2;
    const int lc = (tid & 3) * 8;

    for (int k0 = 0; k0 < K; k0 += 32) {
        __syncthreads();
        {
            const float* hp = Hg + (size_t)lr * K + k0 + lc;
            float4 a0 = *reinterpret_cast<const float4*>(hp);
            float4 a1 = *reinterpret_cast<const float4*>(hp + 4);
            *reinterpret_cast<float4*>(As + lr*AP + lc)     = a0;
            *reinterpret_cast<float4*>(As + lr*AP + lc + 4) = a1;
        }
        constexpr int C4 = COUT / 4;
#pragma unroll
        for (int q = 0; q < COUT/32; q++) {
            int idx = tid + q*256;
            int rr  = idx / C4;
            int cc  = (idx % C4) * 4;
            *reinterpret_cast<float4*>(Bs + rr*BP + cc) =
                *reinterpret_cast<const float4*>(W + (size_t)(k0 + rr)*COUT + cc);
        }
        __syncthreads();
#pragma unroll 8
        for (int kk = 0; kk < 32; kk++) {
            float a[4];
#pragma unroll
            for (int r = 0; r < 4; r++) a[r] = As[(ty*4 + r)*AP + kk];
            float bb[TN];
#pragma unroll
            for (int q = 0; q < TN/4; q++)
                *reinterpret_cast<float4*>(bb + q*4) =
                    *reinterpret_cast<const float4*>(Bs + kk*BP + tx*TN + q*4);
#pragma unroll
            for (int r = 0; r < 4; r++)
#pragma unroll
                for (int j = 0; j < TN; j++)
                    acc[r][j] = fmaf(a[r], bb[j], acc[r][j]);
        }
    }

    __syncthreads();
    float* Ag = sm;
    float* Zs = sm + 64*65;
#pragma unroll
    for (int r = 0; r < 4; r++)
#pragma unroll
        for (int q = 0; q < TN/4; q++)
            *reinterpret_cast<float4*>(Zs + (ty*4 + r)*BP + tx*TN + q*4) =
                *reinterpret_cast<float4*>(&acc[r][q*4]);
    for (int i = tid; i < 4096; i += 256)
        Ag[(i >> 6)*65 + (i & 63)] = g_A[g*4096 + i];
    __syncthreads();

#pragma unroll
    for (int r = 0; r < 4; r++)
#pragma unroll
        for (int j = 0; j < TN; j++) acc[r][j] = 0.f;
#pragma unroll 4
    for (int k = 0; k < 64; k++) {
        float a[4];
#pragma unroll
        for (int r = 0; r < 4; r++) a[r] = Ag[(ty*4 + r)*65 + k];
        float zz[TN];
#pragma unroll
        for (int q = 0; q < TN/4; q++)
            *reinterpret_cast<float4*>(zz + q*4) =
                *reinterpret_cast<const float4*>(Zs + k*BP + tx*TN + q*4);
#pragma unroll
        for (int r = 0; r < 4; r++)
#pragma unroll
            for (int j = 0; j < TN; j++)
                acc[r][j] = fmaf(a[r], zz[j], acc[r][j]);
    }

    float sc[TN], sh[TN];
#pragma unroll
    for (int j = 0; j < TN; j++) {
        int col = tx*TN + j;
        float s = gam[col] * rsqrtf(var[col] + EPSf);
        sc[j] = s;
        sh[j] = (bias[col] - mean[col]) * s + bet[col];
    }
#pragma unroll
    for (int r = 0; r < 4; r++)
#pragma unroll
        for (int j = 0; j < TN; j++)
            acc[r][j] = fmaxf(fmaf(acc[r][j], sc[j], sh[j]), 0.f);

    if (!FINAL) {
#pragma unroll
        for (int r = 0; r < 4; r++)
#pragma unroll
            for (int q = 0; q < TN/4; q++)
                *reinterpret_cast<float4*>(Hout + (size_t)(g*64 + ty*4 + r)*COUT + tx*TN + q*4) =
                    *reinterpret_cast<float4*>(&acc[r][q*4]);
    } else {
        __syncthreads();
        float* Ys = sm;
#pragma unroll
        for (int r = 0; r < 4; r++)
#pragma unroll
            for (int j = 0; j < TN; j++)
                Ys[(ty*4 + r)*64 + tx*TN + j] = acc[r][j];
        __syncthreads();
        float* pooled = sm + 4096;
        if (tid < 64) {
            float s = 0.f;
#pragma unroll 8
            for (int i = 0; i < 64; i++) s += Ys[i*64 + tid];
            pooled[tid] = s * (1.0f / 64.0f);
        }
        __syncthreads();
        if (tid < 2) {
            float l = fcb[tid];
#pragma unroll 8
            for (int j = 0; j < 64; j++) l = fmaf(pooled[j], fcw[j*2 + tid], l);
            pooled[64 + tid] = l;
        }
        __syncthreads();
        if (tid == 0) {
            float l0 = pooled[64], l1 = pooled[65];
            float m  = fmaxf(l0, l1);
            float lse = m + logf(expf(l0 - m) + expf(l1 - m));
            out[g*2 + 0] = l0 - lse;
            out[g*2 + 1] = l1 - lse;
        }
    }
}

// ---------------- host launcher ----------------
extern "C" void kernel_launch(void* const* d_in, const int* in_sizes, int n_in,
                              void* d_out, int out_size) {
    const float* x   = (const float*)d_in[0];
    const int*   ei  = (const int*)  d_in[1];
    const float* ea  = (const float*)d_in[2];
    const float* cw  = (const float*)d_in[4];
    const float* cb  = (const float*)d_in[5];
    const float* W1  = (const float*)d_in[6];
    const float* b1  = (const float*)d_in[7];
    const float* W2  = (const float*)d_in[8];
    const float* b2  = (const float*)d_in[9];
    const float* W3  = (const float*)d_in[10];
    const float* b3  = (const float*)d_in[11];
    const float* g1  = (const float*)d_in[12];
    const float* be1 = (const float*)d_in[13];
    const float* m1  = (const float*)d_in[14];
    const float* v1  = (const float*)d_in[15];
    const float* g2  = (const float*)d_in[16];
    const float* be2 = (const float*)d_in[17];
    const float* m2  = (const float*)d_in[18];
    const float* v2  = (const float*)d_in[19];
    const float* g3  = (const float*)d_in[20];
    const float* be3 = (const float*)d_in[21];
    const float* m3  = (const float*)d_in[22];
    const float* v3  = (const float*)d_in[23];
    const float* fcw = (const float*)d_in[24];
    const float* fcb = (const float*)d_in[25];
    float* out = (float*)d_out;

    const int* srcp = ei;
    const int* dstp = ei + Ec;

    float *ph1, *ph2;
    cudaGetSymbolAddress((void**)&ph1, g_h1);
    cudaGetSymbolAddress((void**)&ph2, g_h2);

    k_deg_init <<<(Nn + 255)/256, 256>>>();
    k_deg_accum<<<Ec/256,        256>>>(dstp, ea);
    k_dinv     <<<(Nn + 255)/256, 256>>>();
    k_buildA   <<<NG, 256>>>(srcp, dstp, ea);
    k_w1r<<<(HIDc*FINc + 255)/256, 256>>>(W1);
    k_wc <<<(32*108 + 255)/256, 256>>>(cw);

    // fused conv + layer1 (tensor cores)
    const int smemF = 33408 * 4;   // 133632 B
    cudaFuncSetAttribute((const void*)k_fused1,
                         cudaFuncAttributeMaxDynamicSharedMemorySize, smemF);
    k_fused1<<<NG, 256, smemF>>>(x, cb, b1, g1, be1, m1, v1);

    const int smem128 = (64*65 + 64*(HIDc + 4)) * 4;   // 50432 B
    const int smem64  = (64*65 + 64*(OUT3c + 4)) * 4;  // 34048 B
    cudaFuncSetAttribute((const void*)k_layer<128, 128, false>,
                         cudaFuncAttributeMaxDynamicSharedMemorySize, smem128);

    k_layer<128, 128, false><<<NG, 256, smem128>>>(ph1, W2, b2, g2, be2, m2, v2,
                                                   ph2, nullptr, nullptr, nullptr);
    k_layer<128, 64, true><<<NG, 256, smem64>>>(ph2, W3, b3, g3, be3, m3, v3,
                                                nullptr, fcw, fcb, out);
}

// round 7
// speedup vs baseline: 1.5855x; 1.5855x over previous
#include <cuda_runtime.h>
#include <cuda_bf16.h>
#include <math.h>
#include <stdint.h>

// ---------------- problem constants ----------------
#define Nn      32768
#define Ll      3000
#define PERG    64
#define NG      512          // Nn / PERG
#define DEGc    16
#define Ec      (Nn*DEGc)    // 524288
#define HIDc    128
#define OUT3c   64
#define REDc    146
#define FINc    4672         // 32*146
#define EPSf    1e-5f
#define TILES   146          // FINc / 32

// ---------------- device scratch (static, no allocs) ----------------
__device__ float g_deg[Nn];
__device__ float g_dinv[Nn];
__device__ float g_A[NG*64*64];                      // 8 MB
__device__ __nv_bfloat16 g_h0[(size_t)Nn * FINc];    // 306 MB (bf16 conv output)
__device__ float g_h1[(size_t)Nn * HIDc];            // 16 MB
__device__ float g_h2[(size_t)Nn * HIDc];            // 16 MB
__device__ __nv_bfloat16 g_Wt[(size_t)HIDc * FINc];  // 1.2 MB: W1^T, bf16
__device__ float g_Wc[32*108];                       // conv weights, tf32, pitch 108

// ---------------- helpers ----------------
__device__ __forceinline__ uint32_t smem_u32(const void* p) {
    uint32_t a;
    asm("{ .reg .u64 t; cvta.to.shared.u64 t, %1; cvt.u32.u64 %0, t; }" : "=r"(a) : "l"(p));
    return a;
}
__device__ __forceinline__ float tf32r(float x) {
    uint32_t u;
    asm("cvt.rna.tf32.f32 %0, %1;" : "=r"(u) : "f"(x));
    return __uint_as_float(u);
}
__device__ __forceinline__ void mma_tf32(float* d, const uint32_t* a, uint32_t b0, uint32_t b1) {
    asm volatile(
        "mma.sync.aligned.m16n8k8.row.col.f32.tf32.tf32.f32 "
        "{%0,%1,%2,%3}, {%4,%5,%6,%7}, {%8,%9}, {%0,%1,%2,%3};"
        : "+f"(d[0]), "+f"(d[1]), "+f"(d[2]), "+f"(d[3])
        : "r"(a[0]), "r"(a[1]), "r"(a[2]), "r"(a[3]), "r"(b0), "r"(b1));
}
__device__ __forceinline__ void mma_bf16(float* d, const uint32_t* a, uint32_t b0, uint32_t b1) {
    asm volatile(
        "mma.sync.aligned.m16n8k16.row.col.f32.bf16.bf16.f32 "
        "{%0,%1,%2,%3}, {%4,%5,%6,%7}, {%8,%9}, {%0,%1,%2,%3};"
        : "+f"(d[0]), "+f"(d[1]), "+f"(d[2]), "+f"(d[3])
        : "r"(a[0]), "r"(a[1]), "r"(a[2]), "r"(a[3]), "r"(b0), "r"(b1));
}
__device__ __forceinline__ void cp16(uint32_t dst, const void* src) {
    asm volatile("cp.async.cg.shared.global [%0], [%1], 16;" :: "r"(dst), "l"(src));
}
#define CP_COMMIT() asm volatile("cp.async.commit_group;" ::: "memory")
#define CP_WAIT1()  asm volatile("cp.async.wait_group 1;" ::: "memory")

// ---------------- degree / dinv ----------------
__global__ void k_deg_init() {
    int i = blockIdx.x * blockDim.x + threadIdx.x;
    if (i < Nn) g_deg[i] = 1.0f;
}
__global__ void k_deg_accum(const int* __restrict__ dst, const float* __restrict__ w) {
    int e = blockIdx.x * blockDim.x + threadIdx.x;
    if (e < Ec) atomicAdd(&g_deg[dst[e]], w[e]);
}
__global__ void k_dinv() {
    int i = blockIdx.x * blockDim.x + threadIdx.x;
    if (i < Nn) g_dinv[i] = rsqrtf(g_deg[i]);
}

// ---------------- per-graph aggregation matrix ----------------
__global__ void __launch_bounds__(256) k_buildA(const int* __restrict__ src,
                                                const int* __restrict__ dst,
                                                const float* __restrict__ w) {
    __shared__ float sA[64*64];
    __shared__ float sdin[64];
    const int g = blockIdx.x, tid = threadIdx.x;
    for (int i = tid; i < 4096; i += 256) sA[i] = 0.f;
    if (tid < 64) sdin[tid] = g_dinv[g*64 + tid];
    __syncthreads();
    const int base = g * (PERG * DEGc);
    for (int e = tid; e < PERG*DEGc; e += 256) {
        int s = src[base + e] - g*64;
        int d = dst[base + e] - g*64;
        float v = sdin[s] * w[base + e] * sdin[d];
        atomicAdd(&sA[d*64 + s], v);
    }
    __syncthreads();
    if (tid < 64) { float di = sdin[tid]; sA[tid*64 + tid] += di*di; }
    __syncthreads();
    for (int i = tid; i < 4096; i += 256) g_A[g*4096 + i] = sA[i];
}

// ---------------- W1 transpose + bf16 round ----------------
__global__ void k_wt(const float* __restrict__ W) {
    __shared__ float t[32][33];
    int k0 = blockIdx.x * 32, n0 = blockIdx.y * 32;
    int tx = threadIdx.x, ty = threadIdx.y;           // 32 x 8
    for (int r = 0; r < 32; r += 8)
        t[ty + r][tx] = W[(size_t)(k0 + ty + r) * HIDc + n0 + tx];
    __syncthreads();
    for (int r = 0; r < 32; r += 8)
        g_Wt[(size_t)(n0 + ty + r) * FINc + k0 + tx] = __float2bfloat16_rn(t[tx][ty + r]);
}

// ---------------- conv weight prep: tf32, pitch 108, zero pad ----------------
__global__ void k_wc(const float* __restrict__ cw) {
    int i = blockIdx.x * blockDim.x + threadIdx.x;
    if (i < 32*108) {
        int c = i / 108, t = i % 108;
        g_Wc[i] = (t < 100) ? tf32r(cw[c*100 + t]) : 0.f;
    }
}

// ---------------- Conv1d via mma.sync tf32, bf16 output ----------------
__global__ void __launch_bounds__(128) k_conv_tc(const float* __restrict__ x,
                                                 const float* __restrict__ cb) {
    __shared__ float sbuf[6740];   // [0,3284) x padded ; [3284,6740) weights pitch 108
    float* xs = sbuf;
    float* ws = sbuf + 3284;
    const int n    = blockIdx.x;
    const int tid  = threadIdx.x;
    const int warp = tid >> 5, lane = tid & 31;
    const int gID  = lane >> 2, tig = lane & 3;

    {
        const float4* x4 = reinterpret_cast<const float4*>(x + (size_t)n * Ll);
        float4* xs4 = reinterpret_cast<float4*>(xs);
        for (int i = tid; i < 750; i += 128) xs4[i] = x4[i];
        for (int i = 3000 + tid; i < 3284; i += 128) xs[i] = 0.f;
        const float4* w4 = reinterpret_cast<const float4*>(g_Wc);
        float4* ws4 = reinterpret_cast<float4*>(ws);
        for (int i = tid; i < 864; i += 128) ws4[i] = w4[i];
    }
    __syncthreads();

    float acc[2][5][4];
#pragma unroll
    for (int mi = 0; mi < 2; mi++)
#pragma unroll
        for (int nt = 0; nt < 5; nt++)
#pragma unroll
            for (int c = 0; c < 4; c++) acc[mi][nt][c] = 0.f;

    const int pbase = warp * 40;
#pragma unroll
    for (int k8 = 0; k8 < 13; k8++) {
        const int k0 = k8 * 8;
        uint32_t a[2][4];
#pragma unroll
        for (int mi = 0; mi < 2; mi++) {
            const int c = mi*16 + gID;
            a[mi][0] = __float_as_uint(ws[c*108 + k0 + tig]);
            a[mi][1] = __float_as_uint(ws[(c+8)*108 + k0 + tig]);
            a[mi][2] = __float_as_uint(ws[c*108 + k0 + tig + 4]);
            a[mi][3] = __float_as_uint(ws[(c+8)*108 + k0 + tig + 4]);
        }
#pragma unroll
        for (int nt = 0; nt < 5; nt++) {
            const int p = pbase + nt*8 + gID;
            uint32_t b0 = __float_as_uint(xs[20*p + k0 + tig]);
            uint32_t b1 = __float_as_uint(xs[20*p + k0 + tig + 4]);
            mma_tf32(acc[0][nt], a[0], b0, b1);
            mma_tf32(acc[1][nt], a[1], b0, b1);
        }
    }

    float bc[2][2];
#pragma unroll
    for (int mi = 0; mi < 2; mi++) {
        bc[mi][0] = cb[mi*16 + gID];
        bc[mi][1] = cb[mi*16 + gID + 8];
    }
    __syncthreads();                       // smem reads done; reuse as bf16 output stage
    __nv_bfloat16* sout = reinterpret_cast<__nv_bfloat16*>(sbuf);   // 4672 bf16 [c][p]
#pragma unroll
    for (int mi = 0; mi < 2; mi++)
#pragma unroll
        for (int nt = 0; nt < 5; nt++) {
            const int c0 = mi*16 + gID, c1 = c0 + 8;
            const int p0 = pbase + nt*8 + 2*tig;      // even
            if (p0 < REDc) {
                bool two = (p0 + 1 < REDc);
                float v00 = fmaxf(acc[mi][nt][0] + bc[mi][0], 0.f);
                float v01 = two ? fmaxf(acc[mi][nt][1] + bc[mi][0], 0.f) : 0.f;
                float v10 = fmaxf(acc[mi][nt][2] + bc[mi][1], 0.f);
                float v11 = two ? fmaxf(acc[mi][nt][3] + bc[mi][1], 0.f) : 0.f;
                if (two) {
                    *reinterpret_cast<__nv_bfloat162*>(sout + c0*REDc + p0) =
                        __floats2bfloat162_rn(v00, v01);
                    *reinterpret_cast<__nv_bfloat162*>(sout + c1*REDc + p0) =
                        __floats2bfloat162_rn(v10, v11);
                } else {
                    sout[c0*REDc + p0] = __float2bfloat16_rn(v00);
                    sout[c1*REDc + p0] = __float2bfloat16_rn(v10);
                }
            }
        }
    __syncthreads();
    uint4* o4 = reinterpret_cast<uint4*>(g_h0 + (size_t)n * FINc);
    const uint4* so4 = reinterpret_cast<const uint4*>(sout);
    for (int i = tid; i < 584; i += 128) o4[i] = so4[i];
}

// ---------------- layer1 via mma.sync bf16 (m16n8k16) ----------------
// CTA = 2 graphs (M=128), N=128, K=4672 bf16. cp.async double-buffered
// K-tiles of 32 bf16. Pitch 40 bf16 = 80 B (16B-aligned rows, conflict-free).
// Stage: A 128x80B = 10240 B, B same -> 20480 B per stage, x2 stages = 40960 B.
__global__ void __launch_bounds__(256, 2) k_layer1_bf(
    const float* __restrict__ bias,
    const float* __restrict__ gam, const float* __restrict__ bet,
    const float* __restrict__ mean, const float* __restrict__ var)
{
    extern __shared__ float smf[];
    const uint32_t sb = smem_u32(smf);
    const int tid  = threadIdx.x;
    const int b    = blockIdx.x;                 // graph pair
    const int warp = tid >> 5, lane = tid & 31;
    const int wm   = warp >> 1, wn = warp & 1;   // 4 x 2 warp grid
    const int gID  = lane >> 2, tig = lane & 3;

    const __nv_bfloat16* Ap = g_h0 + (size_t)b * 128 * FINc;
    const int lr = tid >> 1;                     // 0..127 row
    const int lc = (tid & 1) * 16;               // bf16 col 0 or 16

    auto issue = [&](int i) {
        const int s = i & 1;
        const int k0 = i * 32;
        const uint32_t stb = sb + (uint32_t)s * 20480u;
#pragma unroll
        for (int q = 0; q < 2; q++) {
            int c = lc + q * 8;                  // bf16 col 0,8,16,24
            uint32_t o = (uint32_t)(lr * 80 + c * 2);
            cp16(stb + o,          Ap   + (size_t)lr * FINc + k0 + c);
            cp16(stb + 10240u + o, g_Wt + (size_t)lr * FINc + k0 + c);
        }
    };

    float acc[2][8][4];
#pragma unroll
    for (int mi = 0; mi < 2; mi++)
#pragma unroll
        for (int j = 0; j < 8; j++)
#pragma unroll
            for (int c = 0; c < 4; c++) acc[mi][j][c] = 0.f;

    issue(0); CP_COMMIT();
    issue(1); CP_COMMIT();

    for (int i = 0; i < TILES; i++) {
        CP_WAIT1();
        __syncthreads();
        const __nv_bfloat16* As = reinterpret_cast<const __nv_bfloat16*>(
            reinterpret_cast<const char*>(smf) + (i & 1) * 20480);
        const __nv_bfloat16* Bs = As + 5120;     // +10240 B
#pragma unroll
        for (int kk = 0; kk < 2; kk++) {
            const int k0 = kk * 16;
            uint32_t a[2][4];
#pragma unroll
            for (int mi = 0; mi < 2; mi++) {
                int row = wm*32 + mi*16 + gID;
                a[mi][0] = *reinterpret_cast<const uint32_t*>(As + row*40     + k0 + 2*tig);
                a[mi][1] = *reinterpret_cast<const uint32_t*>(As + (row+8)*40 + k0 + 2*tig);
                a[mi][2] = *reinterpret_cast<const uint32_t*>(As + row*40     + k0 + 8 + 2*tig);
                a[mi][3] = *reinterpret_cast<const uint32_t*>(As + (row+8)*40 + k0 + 8 + 2*tig);
            }
#pragma unroll
            for (int j = 0; j < 8; j++) {
                int n = wn*64 + j*8 + gID;
                uint32_t b0 = *reinterpret_cast<const uint32_t*>(Bs + n*40 + k0 + 2*tig);
                uint32_t b1 = *reinterpret_cast<const uint32_t*>(Bs + n*40 + k0 + 8 + 2*tig);
                mma_bf16(acc[0][j], a[0], b0, b1);
                mma_bf16(acc[1][j], a[1], b0, b1);
            }
        }
        __syncthreads();
        if (i + 2 < TILES) issue(i + 2);
        CP_COMMIT();
    }

    __syncthreads();
    float* Zs = smf;                               // 128 x 130
    float* Ag = smf + 16640;                       // 2 x (64 x 65)
#pragma unroll
    for (int mi = 0; mi < 2; mi++)
#pragma unroll
        for (int j = 0; j < 8; j++) {
            int row = wm*32 + mi*16 + gID;
            int col = wn*64 + j*8 + 2*tig;
            *reinterpret_cast<float2*>(Zs + row*130 + col) =
                make_float2(acc[mi][j][0], acc[mi][j][1]);
            *reinterpret_cast<float2*>(Zs + (row+8)*130 + col) =
                make_float2(acc[mi][j][2], acc[mi][j][3]);
        }
    {
        const float* gA = g_A + (size_t)(2*b) * 4096;
        for (int i2 = tid; i2 < 8192; i2 += 256) {
            int gg = i2 >> 12, rr = (i2 >> 6) & 63, cc = i2 & 63;
            Ag[gg*4160 + rr*65 + cc] = gA[(size_t)gg*4096 + rr*64 + cc];
        }
    }
    __syncthreads();

    {
        const int gg = tid >> 7;
        const int t  = tid & 127;
        const int tx = t & 15;
        const int ty = t >> 4;
        float ac[8][8];
#pragma unroll
        for (int r = 0; r < 8; r++)
#pragma unroll
            for (int j = 0; j < 8; j++) ac[r][j] = 0.f;

        const float* Agg = Ag + gg * 4160;
        const float* Zg  = Zs + gg * 64 * 130;
#pragma unroll 4
        for (int k = 0; k < 64; k++) {
            float a[8], z[8];
#pragma unroll
            for (int r = 0; r < 8; r++) a[r] = Agg[(ty*8 + r)*65 + k];
#pragma unroll
            for (int j = 0; j < 8; j++) z[j] = Zg[k*130 + tx*8 + j];
#pragma unroll
            for (int r = 0; r < 8; r++)
#pragma unroll
                for (int j = 0; j < 8; j++)
                    ac[r][j] = fmaf(a[r], z[j], ac[r][j]);
        }
        float sc[8], sh[8];
#pragma unroll
        for (int j = 0; j < 8; j++) {
            int col = tx*8 + j;
            float s = gam[col] * rsqrtf(var[col] + EPSf);
            sc[j] = s;
            sh[j] = (bias[col] - mean[col]) * s + bet[col];
        }
#pragma unroll
        for (int r = 0; r < 8; r++) {
            float v[8];
#pragma unroll
            for (int j = 0; j < 8; j++)
                v[j] = fmaxf(fmaf(ac[r][j], sc[j], sh[j]), 0.f);
            float* dst = g_h1 + (size_t)(b*128 + gg*64 + ty*8 + r) * HIDc + tx*8;
            *reinterpret_cast<float4*>(dst)     = make_float4(v[0], v[1], v[2], v[3]);
            *reinterpret_cast<float4*>(dst + 4) = make_float4(v[4], v[5], v[6], v[7]);
        }
    }
}

// ---------------- fused GCN layer (fp32, layers 2 & 3) ----------------
template<int K, int COUT, bool FINAL>
__global__ void __launch_bounds__(256) k_layer(
    const float* __restrict__ Hin, const float* __restrict__ W,
    const float* __restrict__ bias,
    const float* __restrict__ gam, const float* __restrict__ bet,
    const float* __restrict__ mean, const float* __restrict__ var,
    float* __restrict__ Hout,
    const float* __restrict__ fcw, const float* __restrict__ fcb,
    float* __restrict__ out)
{
    extern __shared__ float sm[];
    constexpr int TN = COUT / 16;
    constexpr int AP = 36;
    constexpr int BP = COUT + 4;
    float* As = sm;
    float* Bs = sm + 64*AP;

    const int tid = threadIdx.x;
    const int tx  = tid & 15;
    const int ty  = tid >> 4;
    const int g   = blockIdx.x;

    float acc[4][TN];
#pragma unroll
    for (int r = 0; r < 4; r++)
#pragma unroll
        for (int j = 0; j < TN; j++) acc[r][j] = 0.f;

    const float* Hg = Hin + (size_t)g * 64 * K;
    const int lr = tid >> 2;
    const int lc = (tid & 3) * 8;

    for (int k0 = 0; k0 < K; k0 += 32) {
        __syncthreads();
        {
            const float* hp = Hg + (size_t)lr * K + k0 + lc;
            float4 a0 = *reinterpret_cast<const float4*>(hp);
            float4 a1 = *reinterpret_cast<const float4*>(hp + 4);
            *reinterpret_cast<float4*>(As + lr*AP + lc)     = a0;
            *reinterpret_cast<float4*>(As + lr*AP + lc + 4) = a1;
        }
        constexpr int C4 = COUT / 4;
#pragma unroll
        for (int q = 0; q < COUT/32; q++) {
            int idx = tid + q*256;
            int rr  = idx / C4;
            int cc  = (idx % C4) * 4;
            *reinterpret_cast<float4*>(Bs + rr*BP + cc) =
                *reinterpret_cast<const float4*>(W + (size_t)(k0 + rr)*COUT + cc);
        }
        __syncthreads();
#pragma unroll 8
        for (int kk = 0; kk < 32; kk++) {
            float a[4];
#pragma unroll
            for (int r = 0; r < 4; r++) a[r] = As[(ty*4 + r)*AP + kk];
            float bb[TN];
#pragma unroll
            for (int q = 0; q < TN/4; q++)
                *reinterpret_cast<float4*>(bb + q*4) =
                    *reinterpret_cast<const float4*>(Bs + kk*BP + tx*TN + q*4);
#pragma unroll
            for (int r = 0; r < 4; r++)
#pragma unroll
                for (int j = 0; j < TN; j++)
                    acc[r][j] = fmaf(a[r], bb[j], acc[r][j]);
        }
    }

    __syncthreads();
    float* Ag = sm;
    float* Zs = sm + 64*65;
#pragma unroll
    for (int r = 0; r < 4; r++)
#pragma unroll
        for (int q = 0; q < TN/4; q++)
            *reinterpret_cast<float4*>(Zs + (ty*4 + r)*BP + tx*TN + q*4) =
                *reinterpret_cast<float4*>(&acc[r][q*4]);
    for (int i = tid; i < 4096; i += 256)
        Ag[(i >> 6)*65 + (i & 63)] = g_A[g*4096 + i];
    __syncthreads();

#pragma unroll
    for (int r = 0; r < 4; r++)
#pragma unroll
        for (int j = 0; j < TN; j++) acc[r][j] = 0.f;
#pragma unroll 4
    for (int k = 0; k < 64; k++) {
        float a[4];
#pragma unroll
        for (int r = 0; r < 4; r++) a[r] = Ag[(ty*4 + r)*65 + k];
        float zz[TN];
#pragma unroll
        for (int q = 0; q < TN/4; q++)
            *reinterpret_cast<float4*>(zz + q*4) =
                *reinterpret_cast<const float4*>(Zs + k*BP + tx*TN + q*4);
#pragma unroll
        for (int r = 0; r < 4; r++)
#pragma unroll
            for (int j = 0; j < TN; j++)
                acc[r][j] = fmaf(a[r], zz[j], acc[r][j]);
    }

    float sc[TN], sh[TN];
#pragma unroll
    for (int j = 0; j < TN; j++) {
        int col = tx*TN + j;
        float s = gam[col] * rsqrtf(var[col] + EPSf);
        sc[j] = s;
        sh[j] = (bias[col] - mean[col]) * s + bet[col];
    }
#pragma unroll
    for (int r = 0; r < 4; r++)
#pragma unroll
        for (int j = 0; j < TN; j++)
            acc[r][j] = fmaxf(fmaf(acc[r][j], sc[j], sh[j]), 0.f);

    if (!FINAL) {
#pragma unroll
        for (int r = 0; r < 4; r++)
#pragma unroll
            for (int q = 0; q < TN/4; q++)
                *reinterpret_cast<float4*>(Hout + (size_t)(g*64 + ty*4 + r)*COUT + tx*TN + q*4) =
                    *reinterpret_cast<float4*>(&acc[r][q*4]);
    } else {
        __syncthreads();
        float* Ys = sm;
#pragma unroll
        for (int r = 0; r < 4; r++)
#pragma unroll
            for (int j = 0; j < TN; j++)
                Ys[(ty*4 + r)*64 + tx*TN + j] = acc[r][j];
        __syncthreads();
        float* pooled = sm + 4096;
        if (tid < 64) {
            float s = 0.f;
#pragma unroll 8
            for (int i = 0; i < 64; i++) s += Ys[i*64 + tid];
            pooled[tid] = s * (1.0f / 64.0f);
        }
        __syncthreads();
        if (tid < 2) {
            float l = fcb[tid];
#pragma unroll 8
            for (int j = 0; j < 64; j++) l = fmaf(pooled[j], fcw[j*2 + tid], l);
            pooled[64 + tid] = l;
        }
        __syncthreads();
        if (tid == 0) {
            float l0 = pooled[64], l1 = pooled[65];
            float m  = fmaxf(l0, l1);
            float lse = m + logf(expf(l0 - m) + expf(l1 - m));
            out[g*2 + 0] = l0 - lse;
            out[g*2 + 1] = l1 - lse;
        }
    }
}

// ---------------- host launcher ----------------
extern "C" void kernel_launch(void* const* d_in, const int* in_sizes, int n_in,
                              void* d_out, int out_size) {
    const float* x   = (const float*)d_in[0];
    const int*   ei  = (const int*)  d_in[1];
    const float* ea  = (const float*)d_in[2];
    const float* cw  = (const float*)d_in[4];
    const float* cb  = (const float*)d_in[5];
    const float* W1  = (const float*)d_in[6];
    const float* b1  = (const float*)d_in[7];
    const float* W2  = (const float*)d_in[8];
    const float* b2  = (const float*)d_in[9];
    const float* W3  = (const float*)d_in[10];
    const float* b3  = (const float*)d_in[11];
    const float* g1  = (const float*)d_in[12];
    const float* be1 = (const float*)d_in[13];
    const float* m1  = (const float*)d_in[14];
    const float* v1  = (const float*)d_in[15];
    const float* g2  = (const float*)d_in[16];
    const float* be2 = (const float*)d_in[17];
    const float* m2  = (const float*)d_in[18];
    const float* v2  = (const float*)d_in[19];
    const float* g3  = (const float*)d_in[20];
    const float* be3 = (const float*)d_in[21];
    const float* m3  = (const float*)d_in[22];
    const float* v3  = (const float*)d_in[23];
    const float* fcw = (const float*)d_in[24];
    const float* fcb = (const float*)d_in[25];
    float* out = (float*)d_out;

    const int* srcp = ei;
    const int* dstp = ei + Ec;

    float *ph1, *ph2;
    cudaGetSymbolAddress((void**)&ph1, g_h1);
    cudaGetSymbolAddress((void**)&ph2, g_h2);

    k_deg_init <<<(Nn + 255)/256, 256>>>();
    k_deg_accum<<<Ec/256,        256>>>(dstp, ea);
    k_dinv     <<<(Nn + 255)/256, 256>>>();
    k_buildA   <<<NG, 256>>>(srcp, dstp, ea);
    {
        dim3 tb(32, 8);
        dim3 gb(FINc/32, HIDc/32);
        k_wt<<<gb, tb>>>(W1);
    }
    k_wc<<<(32*108 + 255)/256, 256>>>(cw);
    k_conv_tc<<<Nn, 128>>>(x, cb);

    // layer 1 on tensor cores (mma.sync bf16)
    const int smemL1 = (128*130 + 2*64*65) * 4;   // 99840 B (epilogue dominates)
    cudaFuncSetAttribute((const void*)k_layer1_bf,
                         cudaFuncAttributeMaxDynamicSharedMemorySize, smemL1);
    k_layer1_bf<<<NG/2, 256, smemL1>>>(b1, g1, be1, m1, v1);

    const int smem128 = (64*65 + 64*(HIDc + 4)) * 4;   // 50432 B
    const int smem64  = (64*65 + 64*(OUT3c + 4)) * 4;  // 34048 B
    cudaFuncSetAttribute((const void*)k_layer<128, 128, false>,
                         cudaFuncAttributeMaxDynamicSharedMemorySize, smem128);

    k_layer<128, 128, false><<<NG, 256, smem128>>>(ph1, W2, b2, g2, be2, m2, v2,
                                                   ph2, nullptr, nullptr, nullptr);
    k_layer<128, 64, true><<<NG, 256, smem64>>>(ph2, W3, b3, g3, be3, m3, v3,
                                                nullptr, fcw, fcb, out);
}

// round 8
// speedup vs baseline: 1.6305x; 1.0284x over previous
#include <cuda_runtime.h>
#include <cuda_fp16.h>
#include <math.h>
#include <stdint.h>

// ---------------- problem constants ----------------
#define Nn      32768
#define Ll      3000
#define PERG    64
#define NG      512          // Nn / PERG
#define DEGc    16
#define Ec      (Nn*DEGc)    // 524288
#define HIDc    128
#define OUT3c   64
#define REDc    146
#define FINc    4672         // 32*146
#define EPSf    1e-5f
#define TILES   146          // FINc / 32
#define WCP     120          // conv weight pitch (halves)

// ---------------- device scratch (static, no allocs) ----------------
__device__ float g_deg[Nn];
__device__ float g_dinv[Nn];
__device__ float g_A[NG*64*64];                 // 8 MB
__device__ __half g_h0[(size_t)Nn * FINc];      // 306 MB (fp16 conv output)
__device__ float g_h1[(size_t)Nn * HIDc];       // 16 MB
__device__ float g_h2[(size_t)Nn * HIDc];       // 16 MB
__device__ __half g_Wt[(size_t)HIDc * FINc];    // 1.2 MB: W1^T, fp16
__device__ __half g_Wch[32*WCP];                // conv weights fp16, pitch 120, zero pad

// ---------------- helpers ----------------
__device__ __forceinline__ uint32_t smem_u32(const void* p) {
    uint32_t a;
    asm("{ .reg .u64 t; cvta.to.shared.u64 t, %1; cvt.u32.u64 %0, t; }" : "=r"(a) : "l"(p));
    return a;
}
__device__ __forceinline__ void mma_f16(float* d, const uint32_t* a, uint32_t b0, uint32_t b1) {
    asm volatile(
        "mma.sync.aligned.m16n8k16.row.col.f32.f16.f16.f32 "
        "{%0,%1,%2,%3}, {%4,%5,%6,%7}, {%8,%9}, {%0,%1,%2,%3};"
        : "+f"(d[0]), "+f"(d[1]), "+f"(d[2]), "+f"(d[3])
        : "r"(a[0]), "r"(a[1]), "r"(a[2]), "r"(a[3]), "r"(b0), "r"(b1));
}
__device__ __forceinline__ void cp16(uint32_t dst, const void* src) {
    asm volatile("cp.async.cg.shared.global [%0], [%1], 16;" :: "r"(dst), "l"(src));
}
#define CP_COMMIT() asm volatile("cp.async.commit_group;" ::: "memory")
#define CP_WAIT1()  asm volatile("cp.async.wait_group 1;" ::: "memory")

// ---------------- degree / dinv ----------------
__global__ void k_deg_init() {
    int i = blockIdx.x * blockDim.x + threadIdx.x;
    if (i < Nn) g_deg[i] = 1.0f;
}
__global__ void k_deg_accum(const int* __restrict__ dst, const float* __restrict__ w) {
    int e = blockIdx.x * blockDim.x + threadIdx.x;
    if (e < Ec) atomicAdd(&g_deg[dst[e]], w[e]);
}
__global__ void k_dinv() {
    int i = blockIdx.x * blockDim.x + threadIdx.x;
    if (i < Nn) g_dinv[i] = rsqrtf(g_deg[i]);
}

// ---------------- per-graph aggregation matrix ----------------
__global__ void __launch_bounds__(256) k_buildA(const int* __restrict__ src,
                                                const int* __restrict__ dst,
                                                const float* __restrict__ w) {
    __shared__ float sA[64*64];
    __shared__ float sdin[64];
    const int g = blockIdx.x, tid = threadIdx.x;
    for (int i = tid; i < 4096; i += 256) sA[i] = 0.f;
    if (tid < 64) sdin[tid] = g_dinv[g*64 + tid];
    __syncthreads();
    const int base = g * (PERG * DEGc);
    for (int e = tid; e < PERG*DEGc; e += 256) {
        int s = src[base + e] - g*64;
        int d = dst[base + e] - g*64;
        float v = sdin[s] * w[base + e] * sdin[d];
        atomicAdd(&sA[d*64 + s], v);
    }
    __syncthreads();
    if (tid < 64) { float di = sdin[tid]; sA[tid*64 + tid] += di*di; }
    __syncthreads();
    for (int i = tid; i < 4096; i += 256) g_A[g*4096 + i] = sA[i];
}

// ---------------- W1 transpose + fp16 round ----------------
__global__ void k_wt(const float* __restrict__ W) {
    __shared__ float t[32][33];
    int k0 = blockIdx.x * 32, n0 = blockIdx.y * 32;
    int tx = threadIdx.x, ty = threadIdx.y;           // 32 x 8
    for (int r = 0; r < 32; r += 8)
        t[ty + r][tx] = W[(size_t)(k0 + ty + r) * HIDc + n0 + tx];
    __syncthreads();
    for (int r = 0; r < 32; r += 8)
        g_Wt[(size_t)(n0 + ty + r) * FINc + k0 + tx] = __float2half_rn(t[tx][ty + r]);
}

// ---------------- conv weight prep: fp16, pitch 120, zero pad ----------------
__global__ void k_wc(const float* __restrict__ cw) {
    int i = blockIdx.x * blockDim.x + threadIdx.x;
    if (i < 32*WCP) {
        int c = i / WCP, t = i % WCP;
        g_Wch[i] = __float2half_rn((t < 100) ? cw[c*100 + t] : 0.f);
    }
}

// ---------------- Conv1d via mma.sync fp16 (m16n8k16), fp16 output ----------------
// One CTA (128 thr, 4 warps) per node. M=32 filters, N=160 p (warp=40),
// K=112 (7 k16 steps). B fragment = implicit im2col: B[k=t][n=p] = xs[20p + t].
__global__ void __launch_bounds__(128) k_conv_tc(const float* __restrict__ x,
                                                 const float* __restrict__ cb) {
    __shared__ __half sbuf[3304 + 32*WCP];   // xs [0,3304) ; ws [3304, 3304+3840)
    __half* xs = sbuf;
    __half* ws = sbuf + 3304;
    const int n    = blockIdx.x;
    const int tid  = threadIdx.x;
    const int warp = tid >> 5, lane = tid & 31;
    const int gID  = lane >> 2, tig = lane & 3;

    {
        const float4* x4 = reinterpret_cast<const float4*>(x + (size_t)n * Ll);
        for (int i = tid; i < 750; i += 128) {
            float4 v = x4[i];
            __half2* d = reinterpret_cast<__half2*>(xs + i*4);
            d[0] = __floats2half2_rn(v.x, v.y);
            d[1] = __floats2half2_rn(v.z, v.w);
        }
        __half2 z2 = __floats2half2_rn(0.f, 0.f);
        for (int i = 1500 + tid; i < 1652; i += 128)
            reinterpret_cast<__half2*>(xs)[i] = z2;   // pad 3000..3303
        const uint4* w4 = reinterpret_cast<const uint4*>(g_Wch);
        uint4* ws4 = reinterpret_cast<uint4*>(ws);
        for (int i = tid; i < 480; i += 128) ws4[i] = w4[i];   // 3840 halves
    }
    __syncthreads();

    float acc[2][5][4];
#pragma unroll
    for (int mi = 0; mi < 2; mi++)
#pragma unroll
        for (int nt = 0; nt < 5; nt++)
#pragma unroll
            for (int c = 0; c < 4; c++) acc[mi][nt][c] = 0.f;

    const int pbase = warp * 40;
#pragma unroll
    for (int k16 = 0; k16 < 7; k16++) {
        const int k0 = k16 * 16;
        uint32_t a[2][4];
#pragma unroll
        for (int mi = 0; mi < 2; mi++) {
            const int c = mi*16 + gID;
            a[mi][0] = *reinterpret_cast<const uint32_t*>(ws + c*WCP     + k0 + 2*tig);
            a[mi][1] = *reinterpret_cast<const uint32_t*>(ws + (c+8)*WCP + k0 + 2*tig);
            a[mi][2] = *reinterpret_cast<const uint32_t*>(ws + c*WCP     + k0 + 8 + 2*tig);
            a[mi][3] = *reinterpret_cast<const uint32_t*>(ws + (c+8)*WCP + k0 + 8 + 2*tig);
        }
#pragma unroll
        for (int nt = 0; nt < 5; nt++) {
            const int p = pbase + nt*8 + gID;
            uint32_t b0 = *reinterpret_cast<const uint32_t*>(xs + 20*p + k0 + 2*tig);
            uint32_t b1 = *reinterpret_cast<const uint32_t*>(xs + 20*p + k0 + 8 + 2*tig);
            mma_f16(acc[0][nt], a[0], b0, b1);
            mma_f16(acc[1][nt], a[1], b0, b1);
        }
    }

    float bc[2][2];
#pragma unroll
    for (int mi = 0; mi < 2; mi++) {
        bc[mi][0] = cb[mi*16 + gID];
        bc[mi][1] = cb[mi*16 + gID + 8];
    }
    __syncthreads();                       // smem reads done; reuse as fp16 output stage
    __half* sout = sbuf;                   // 4672 fp16 [c][p]
#pragma unroll
    for (int mi = 0; mi < 2; mi++)
#pragma unroll
        for (int nt = 0; nt < 5; nt++) {
            const int c0 = mi*16 + gID, c1 = c0 + 8;
            const int p0 = pbase + nt*8 + 2*tig;      // even
            if (p0 < REDc) {
                bool two = (p0 + 1 < REDc);
                float v00 = fmaxf(acc[mi][nt][0] + bc[mi][0], 0.f);
                float v01 = two ? fmaxf(acc[mi][nt][1] + bc[mi][0], 0.f) : 0.f;
                float v10 = fmaxf(acc[mi][nt][2] + bc[mi][1], 0.f);
                float v11 = two ? fmaxf(acc[mi][nt][3] + bc[mi][1], 0.f) : 0.f;
                if (two) {
                    *reinterpret_cast<__half2*>(sout + c0*REDc + p0) = __floats2half2_rn(v00, v01);
                    *reinterpret_cast<__half2*>(sout + c1*REDc + p0) = __floats2half2_rn(v10, v11);
                } else {
                    sout[c0*REDc + p0] = __float2half_rn(v00);
                    sout[c1*REDc + p0] = __float2half_rn(v10);
                }
            }
        }
    __syncthreads();
    uint4* o4 = reinterpret_cast<uint4*>(g_h0 + (size_t)n * FINc);
    const uint4* so4 = reinterpret_cast<const uint4*>(sout);
    for (int i = tid; i < 584; i += 128) o4[i] = so4[i];
}

// ---------------- layer1 via mma.sync fp16 (m16n8k16) ----------------
// CTA = 2 graphs (M=128), N=128, K=4672 fp16. cp.async double-buffered
// K-tiles of 32. Pitch 40 halves = 80 B. Stage 20480 B, x2.
__global__ void __launch_bounds__(256, 2) k_layer1_hf(
    const float* __restrict__ bias,
    const float* __restrict__ gam, const float* __restrict__ bet,
    const float* __restrict__ mean, const float* __restrict__ var)
{
    extern __shared__ float smf[];
    const uint32_t sb = smem_u32(smf);
    const int tid  = threadIdx.x;
    const int b    = blockIdx.x;                 // graph pair
    const int warp = tid >> 5, lane = tid & 31;
    const int wm   = warp >> 1, wn = warp & 1;   // 4 x 2 warp grid
    const int gID  = lane >> 2, tig = lane & 3;

    const __half* Ap = g_h0 + (size_t)b * 128 * FINc;
    const int lr = tid >> 1;                     // 0..127 row
    const int lc = (tid & 1) * 16;               // col 0 or 16

    auto issue = [&](int i) {
        const int s = i & 1;
        const int k0 = i * 32;
        const uint32_t stb = sb + (uint32_t)s * 20480u;
#pragma unroll
        for (int q = 0; q < 2; q++) {
            int c = lc + q * 8;                  // col 0,8,16,24
            uint32_t o = (uint32_t)(lr * 80 + c * 2);
            cp16(stb + o,          Ap   + (size_t)lr * FINc + k0 + c);
            cp16(stb + 10240u + o, g_Wt + (size_t)lr * FINc + k0 + c);
        }
    };

    float acc[2][8][4];
#pragma unroll
    for (int mi = 0; mi < 2; mi++)
#pragma unroll
        for (int j = 0; j < 8; j++)
#pragma unroll
            for (int c = 0; c < 4; c++) acc[mi][j][c] = 0.f;

    issue(0); CP_COMMIT();
    issue(1); CP_COMMIT();

    for (int i = 0; i < TILES; i++) {
        CP_WAIT1();
        __syncthreads();
        const __half* As = reinterpret_cast<const __half*>(
            reinterpret_cast<const char*>(smf) + (i & 1) * 20480);
        const __half* Bs = As + 5120;            // +10240 B
#pragma unroll
        for (int kk = 0; kk < 2; kk++) {
            const int k0 = kk * 16;
            uint32_t a[2][4];
#pragma unroll
            for (int mi = 0; mi < 2; mi++) {
                int row = wm*32 + mi*16 + gID;
                a[mi][0] = *reinterpret_cast<const uint32_t*>(As + row*40     + k0 + 2*tig);
                a[mi][1] = *reinterpret_cast<const uint32_t*>(As + (row+8)*40 + k0 + 2*tig);
                a[mi][2] = *reinterpret_cast<const uint32_t*>(As + row*40     + k0 + 8 + 2*tig);
                a[mi][3] = *reinterpret_cast<const uint32_t*>(As + (row+8)*40 + k0 + 8 + 2*tig);
            }
#pragma unroll
            for (int j = 0; j < 8; j++) {
                int n = wn*64 + j*8 + gID;
                uint32_t b0 = *reinterpret_cast<const uint32_t*>(Bs + n*40 + k0 + 2*tig);
                uint32_t b1 = *reinterpret_cast<const uint32_t*>(Bs + n*40 + k0 + 8 + 2*tig);
                mma_f16(acc[0][j], a[0], b0, b1);
                mma_f16(acc[1][j], a[1], b0, b1);
            }
        }
        __syncthreads();
        if (i + 2 < TILES) issue(i + 2);
        CP_COMMIT();
    }

    __syncthreads();
    float* Zs = smf;                               // 128 x 130
    float* Ag = smf + 16640;                       // 2 x (64 x 65)
#pragma unroll
    for (int mi = 0; mi < 2; mi++)
#pragma unroll
        for (int j = 0; j < 8; j++) {
            int row = wm*32 + mi*16 + gID;
            int col = wn*64 + j*8 + 2*tig;
            *reinterpret_cast<float2*>(Zs + row*130 + col) =
                make_float2(acc[mi][j][0], acc[mi][j][1]);
            *reinterpret_cast<float2*>(Zs + (row+8)*130 + col) =
                make_float2(acc[mi][j][2], acc[mi][j][3]);
        }
    {
        const float* gA = g_A + (size_t)(2*b) * 4096;
        for (int i2 = tid; i2 < 8192; i2 += 256) {
            int gg = i2 >> 12, rr = (i2 >> 6) & 63, cc = i2 & 63;
            Ag[gg*4160 + rr*65 + cc] = gA[(size_t)gg*4096 + rr*64 + cc];
        }
    }
    __syncthreads();

    {
        const int gg = tid >> 7;
        const int t  = tid & 127;
        const int tx = t & 15;
        const int ty = t >> 4;
        float ac[8][8];
#pragma unroll
        for (int r = 0; r < 8; r++)
#pragma unroll
            for (int j = 0; j < 8; j++) ac[r][j] = 0.f;

        const float* Agg = Ag + gg * 4160;
        const float* Zg  = Zs + gg * 64 * 130;
#pragma unroll 4
        for (int k = 0; k < 64; k++) {
            float a[8], z[8];
#pragma unroll
            for (int r = 0; r < 8; r++) a[r] = Agg[(ty*8 + r)*65 + k];
#pragma unroll
            for (int j = 0; j < 8; j++) z[j] = Zg[k*130 + tx*8 + j];
#pragma unroll
            for (int r = 0; r < 8; r++)
#pragma unroll
                for (int j = 0; j < 8; j++)
                    ac[r][j] = fmaf(a[r], z[j], ac[r][j]);
        }
        float sc[8], sh[8];
#pragma unroll
        for (int j = 0; j < 8; j++) {
            int col = tx*8 + j;
            float s = gam[col] * rsqrtf(var[col] + EPSf);
            sc[j] = s;
            sh[j] = (bias[col] - mean[col]) * s + bet[col];
        }
#pragma unroll
        for (int r = 0; r < 8; r++) {
            float v[8];
#pragma unroll
            for (int j = 0; j < 8; j++)
                v[j] = fmaxf(fmaf(ac[r][j], sc[j], sh[j]), 0.f);
            float* dst = g_h1 + (size_t)(b*128 + gg*64 + ty*8 + r) * HIDc + tx*8;
            *reinterpret_cast<float4*>(dst)     = make_float4(v[0], v[1], v[2], v[3]);
            *reinterpret_cast<float4*>(dst + 4) = make_float4(v[4], v[5], v[6], v[7]);
        }
    }
}

// ---------------- fused GCN layer (fp32, layers 2 & 3) ----------------
template<int K, int COUT, bool FINAL>
__global__ void __launch_bounds__(256) k_layer(
    const float* __restrict__ Hin, const float* __restrict__ W,
    const float* __restrict__ bias,
    const float* __restrict__ gam, const float* __restrict__ bet,
    const float* __restrict__ mean, const float* __restrict__ var,
    float* __restrict__ Hout,
    const float* __restrict__ fcw, const float* __restrict__ fcb,
    float* __restrict__ out)
{
    extern __shared__ float sm[];
    constexpr int TN = COUT / 16;
    constexpr int AP = 36;
    constexpr int BP = COUT + 4;
    float* As = sm;
    float* Bs = sm + 64*AP;

    const int tid = threadIdx.x;
    const int tx  = tid & 15;
    const int ty  = tid >> 4;
    const int g   = blockIdx.x;

    float acc[4][TN];
#pragma unroll
    for (int r = 0; r < 4; r++)
#pragma unroll
        for (int j = 0; j < TN; j++) acc[r][j] = 0.f;

    const float* Hg = Hin + (size_t)g * 64 * K;
    const int lr = tid >> 2;
    const int lc = (tid & 3) * 8;

    for (int k0 = 0; k0 < K; k0 += 32) {
        __syncthreads();
        {
            const float* hp = Hg + (size_t)lr * K + k0 + lc;
            float4 a0 = *reinterpret_cast<const float4*>(hp);
            float4 a1 = *reinterpret_cast<const float4*>(hp + 4);
            *reinterpret_cast<float4*>(As + lr*AP + lc)     = a0;
            *reinterpret_cast<float4*>(As + lr*AP + lc + 4) = a1;
        }
        constexpr int C4 = COUT / 4;
#pragma unroll
        for (int q = 0; q < COUT/32; q++) {
            int idx = tid + q*256;
            int rr  = idx / C4;
            int cc  = (idx % C4) * 4;
            *reinterpret_cast<float4*>(Bs + rr*BP + cc) =
                *reinterpret_cast<const float4*>(W + (size_t)(k0 + rr)*COUT + cc);
        }
        __syncthreads();
#pragma unroll 8
        for (int kk = 0; kk < 32; kk++) {
            float a[4];
#pragma unroll
            for (int r = 0; r < 4; r++) a[r] = As[(ty*4 + r)*AP + kk];
            float bb[TN];
#pragma unroll
            for (int q = 0; q < TN/4; q++)
                *reinterpret_cast<float4*>(bb + q*4) =
                    *reinterpret_cast<const float4*>(Bs + kk*BP + tx*TN + q*4);
#pragma unroll
            for (int r = 0; r < 4; r++)
#pragma unroll
                for (int j = 0; j < TN; j++)
                    acc[r][j] = fmaf(a[r], bb[j], acc[r][j]);
        }
    }

    __syncthreads();
    float* Ag = sm;
    float* Zs = sm + 64*65;
#pragma unroll
    for (int r = 0; r < 4; r++)
#pragma unroll
        for (int q = 0; q < TN/4; q++)
            *reinterpret_cast<float4*>(Zs + (ty*4 + r)*BP + tx*TN + q*4) =
                *reinterpret_cast<float4*>(&acc[r][q*4]);
    for (int i = tid; i < 4096; i += 256)
        Ag[(i >> 6)*65 + (i & 63)] = g_A[g*4096 + i];
    __syncthreads();

#pragma unroll
    for (int r = 0; r < 4; r++)
#pragma unroll
        for (int j = 0; j < TN; j++) acc[r][j] = 0.f;
#pragma unroll 4
    for (int k = 0; k < 64; k++) {
        float a[4];
#pragma unroll
        for (int r = 0; r < 4; r++) a[r] = Ag[(ty*4 + r)*65 + k];
        float zz[TN];
#pragma unroll
        for (int q = 0; q < TN/4; q++)
            *reinterpret_cast<float4*>(zz + q*4) =
                *reinterpret_cast<const float4*>(Zs + k*BP + tx*TN + q*4);
#pragma unroll
        for (int r = 0; r < 4; r++)
#pragma unroll
            for (int j = 0; j < TN; j++)
                acc[r][j] = fmaf(a[r], zz[j], acc[r][j]);
    }

    float sc[TN], sh[TN];
#pragma unroll
    for (int j = 0; j < TN; j++) {
        int col = tx*TN + j;
        float s = gam[col] * rsqrtf(var[col] + EPSf);
        sc[j] = s;
        sh[j] = (bias[col] - mean[col]) * s + bet[col];
    }
#pragma unroll
    for (int r = 0; r < 4; r++)
#pragma unroll
        for (int j = 0; j < TN; j++)
            acc[r][j] = fmaxf(fmaf(acc[r][j], sc[j], sh[j]), 0.f);

    if (!FINAL) {
#pragma unroll
        for (int r = 0; r < 4; r++)
#pragma unroll
            for (int q = 0; q < TN/4; q++)
                *reinterpret_cast<float4*>(Hout + (size_t)(g*64 + ty*4 + r)*COUT + tx*TN + q*4) =
                    *reinterpret_cast<float4*>(&acc[r][q*4]);
    } else {
        __syncthreads();
        float* Ys = sm;
#pragma unroll
        for (int r = 0; r < 4; r++)
#pragma unroll
            for (int j = 0; j < TN; j++)
                Ys[(ty*4 + r)*64 + tx*TN + j] = acc[r][j];
        __syncthreads();
        float* pooled = sm + 4096;
        if (tid < 64) {
            float s = 0.f;
#pragma unroll 8
            for (int i = 0; i < 64; i++) s += Ys[i*64 + tid];
            pooled[tid] = s * (1.0f / 64.0f);
        }
        __syncthreads();
        if (tid < 2) {
            float l = fcb[tid];
#pragma unroll 8
            for (int j = 0; j < 64; j++) l = fmaf(pooled[j], fcw[j*2 + tid], l);
            pooled[64 + tid] = l;
        }
        __syncthreads();
        if (tid == 0) {
            float l0 = pooled[64], l1 = pooled[65];
            float m  = fmaxf(l0, l1);
            float lse = m + logf(expf(l0 - m) + expf(l1 - m));
            out[g*2 + 0] = l0 - lse;
            out[g*2 + 1] = l1 - lse;
        }
    }
}

// ---------------- host launcher ----------------
extern "C" void kernel_launch(void* const* d_in, const int* in_sizes, int n_in,
                              void* d_out, int out_size) {
    const float* x   = (const float*)d_in[0];
    const int*   ei  = (const int*)  d_in[1];
    const float* ea  = (const float*)d_in[2];
    const float* cw  = (const float*)d_in[4];
    const float* cb  = (const float*)d_in[5];
    const float* W1  = (const float*)d_in[6];
    const float* b1  = (const float*)d_in[7];
    const float* W2  = (const float*)d_in[8];
    const float* b2  = (const float*)d_in[9];
    const float* W3  = (const float*)d_in[10];
    const float* b3  = (const float*)d_in[11];
    const float* g1  = (const float*)d_in[12];
    const float* be1 = (const float*)d_in[13];
    const float* m1  = (const float*)d_in[14];
    const float* v1  = (const float*)d_in[15];
    const float* g2  = (const float*)d_in[16];
    const float* be2 = (const float*)d_in[17];
    const float* m2  = (const float*)d_in[18];
    const float* v2  = (const float*)d_in[19];
    const float* g3  = (const float*)d_in[20];
    const float* be3 = (const float*)d_in[21];
    const float* m3  = (const float*)d_in[22];
    const float* v3  = (const float*)d_in[23];
    const float* fcw = (const float*)d_in[24];
    const float* fcb = (const float*)d_in[25];
    float* out = (float*)d_out;

    const int* srcp = ei;
    const int* dstp = ei + Ec;

    float *ph1, *ph2;
    cudaGetSymbolAddress((void**)&ph1, g_h1);
    cudaGetSymbolAddress((void**)&ph2, g_h2);

    k_deg_init <<<(Nn + 255)/256, 256>>>();
    k_deg_accum<<<Ec/256,        256>>>(dstp, ea);
    k_dinv     <<<(Nn + 255)/256, 256>>>();
    k_buildA   <<<NG, 256>>>(srcp, dstp, ea);
    {
        dim3 tb(32, 8);
        dim3 gb(FINc/32, HIDc/32);
        k_wt<<<gb, tb>>>(W1);
    }
    k_wc<<<(32*WCP + 255)/256, 256>>>(cw);
    k_conv_tc<<<Nn, 128>>>(x, cb);

    // layer 1 on tensor cores (mma.sync fp16)
    const int smemL1 = (128*130 + 2*64*65) * 4;   // 99840 B (epilogue dominates)
    cudaFuncSetAttribute((const void*)k_layer1_hf,
                         cudaFuncAttributeMaxDynamicSharedMemorySize, smemL1);
    k_layer1_hf<<<NG/2, 256, smemL1>>>(b1, g1, be1, m1, v1);

    const int smem128 = (64*65 + 64*(HIDc + 4)) * 4;   // 50432 B
    const int smem64  = (64*65 + 64*(OUT3c + 4)) * 4;  // 34048 B
    cudaFuncSetAttribute((const void*)k_layer<128, 128, false>,
                         cudaFuncAttributeMaxDynamicSharedMemorySize, smem128);

    k_layer<128, 128, false><<<NG, 256, smem128>>>(ph1, W2, b2, g2, be2, m2, v2,
                                                   ph2, nullptr, nullptr, nullptr);
    k_layer<128, 64, true><<<NG, 256, smem64>>>(ph2, W3, b3, g3, be3, m3, v3,
                                                nullptr, fcw, fcb, out);
}

// round 9
// speedup vs baseline: 1.6660x; 1.0217x over previous
#include <cuda_runtime.h>
#include <cuda_fp16.h>
#include <math.h>
#include <stdint.h>

// ---------------- problem constants ----------------
#define Nn      32768
#define Ll      3000
#define PERG    64
#define NG      512          // Nn / PERG
#define DEGc    16
#define Ec      (Nn*DEGc)    // 524288
#define HIDc    128
#define OUT3c   64
#define REDc    146
#define FINc    4672         // 32*146
#define EPSf    1e-5f
#define TILES   146          // FINc / 32
#define WCP     120          // conv weight pitch (halves)

// ---------------- device scratch (static, no allocs) ----------------
__device__ float g_A[NG*64*64];                 // 8 MB
__device__ __half g_h0[(size_t)Nn * FINc];      // 306 MB (fp16 conv output)
__device__ float g_h1[(size_t)Nn * HIDc];       // 16 MB
__device__ __half g_Wt[(size_t)HIDc * FINc];    // 1.2 MB: W1^T, fp16
__device__ __half g_Wch[32*WCP];                // conv weights fp16, pitch 120, zero pad

// ---------------- helpers ----------------
__device__ __forceinline__ uint32_t smem_u32(const void* p) {
    uint32_t a;
    asm("{ .reg .u64 t; cvta.to.shared.u64 t, %1; cvt.u32.u64 %0, t; }" : "=r"(a) : "l"(p));
    return a;
}
__device__ __forceinline__ void mma_f16(float* d, const uint32_t* a, uint32_t b0, uint32_t b1) {
    asm volatile(
        "mma.sync.aligned.m16n8k16.row.col.f32.f16.f16.f32 "
        "{%0,%1,%2,%3}, {%4,%5,%6,%7}, {%8,%9}, {%0,%1,%2,%3};"
        : "+f"(d[0]), "+f"(d[1]), "+f"(d[2]), "+f"(d[3])
        : "r"(a[0]), "r"(a[1]), "r"(a[2]), "r"(a[3]), "r"(b0), "r"(b1));
}
__device__ __forceinline__ void cp16(uint32_t dst, const void* src) {
    asm volatile("cp.async.cg.shared.global [%0], [%1], 16;" :: "r"(dst), "l"(src));
}
#define CP_COMMIT() asm volatile("cp.async.commit_group;" ::: "memory")
#define CP_WAIT1()  asm volatile("cp.async.wait_group 1;" ::: "memory")

// ---------------- per-graph aggregation matrix (deg computed locally) ----------------
__global__ void __launch_bounds__(256) k_buildA(const int* __restrict__ src,
                                                const int* __restrict__ dst,
                                                const float* __restrict__ w) {
    __shared__ float sA[64*64];
    __shared__ float sdeg[64];
    const int g = blockIdx.x, tid = threadIdx.x;
    for (int i = tid; i < 4096; i += 256) sA[i] = 0.f;
    if (tid < 64) sdeg[tid] = 1.0f;               // self-loop weight
    __syncthreads();
    const int base = g * (PERG * DEGc);           // 1024 edges, block-local
    for (int e = tid; e < PERG*DEGc; e += 256)
        atomicAdd(&sdeg[dst[base + e] - g*64], w[base + e]);
    __syncthreads();
    if (tid < 64) sdeg[tid] = rsqrtf(sdeg[tid]);  // now sdin
    __syncthreads();
    for (int e = tid; e < PERG*DEGc; e += 256) {
        int s = src[base + e] - g*64;
        int d = dst[base + e] - g*64;
        atomicAdd(&sA[d*64 + s], sdeg[s] * w[base + e] * sdeg[d]);
    }
    __syncthreads();
    if (tid < 64) { float di = sdeg[tid]; sA[tid*64 + tid] += di*di; }
    __syncthreads();
    for (int i = tid; i < 4096; i += 256) g_A[g*4096 + i] = sA[i];
}

// ---------------- W1 transpose + fp16 round ----------------
__global__ void k_wt(const float* __restrict__ W) {
    __shared__ float t[32][33];
    int k0 = blockIdx.x * 32, n0 = blockIdx.y * 32;
    int tx = threadIdx.x, ty = threadIdx.y;           // 32 x 8
    for (int r = 0; r < 32; r += 8)
        t[ty + r][tx] = W[(size_t)(k0 + ty + r) * HIDc + n0 + tx];
    __syncthreads();
    for (int r = 0; r < 32; r += 8)
        g_Wt[(size_t)(n0 + ty + r) * FINc + k0 + tx] = __float2half_rn(t[tx][ty + r]);
}

// ---------------- conv weight prep: fp16, pitch 120, zero pad ----------------
__global__ void k_wc(const float* __restrict__ cw) {
    int i = blockIdx.x * blockDim.x + threadIdx.x;
    if (i < 32*WCP) {
        int c = i / WCP, t = i % WCP;
        g_Wch[i] = __float2half_rn((t < 100) ? cw[c*100 + t] : 0.f);
    }
}

// ---------------- Conv1d via mma.sync fp16 (m16n8k16), fp16 output ----------------
__global__ void __launch_bounds__(128) k_conv_tc(const float* __restrict__ x,
                                                 const float* __restrict__ cb) {
    __shared__ __half sbuf[3304 + 32*WCP];   // xs [0,3304) ; ws [3304,+3840)
    __half* xs = sbuf;
    __half* ws = sbuf + 3304;
    const int n    = blockIdx.x;
    const int tid  = threadIdx.x;
    const int warp = tid >> 5, lane = tid & 31;
    const int gID  = lane >> 2, tig = lane & 3;

    {
        const float4* x4 = reinterpret_cast<const float4*>(x + (size_t)n * Ll);
        for (int i = tid; i < 750; i += 128) {
            float4 v = x4[i];
            __half2* d = reinterpret_cast<__half2*>(xs + i*4);
            d[0] = __floats2half2_rn(v.x, v.y);
            d[1] = __floats2half2_rn(v.z, v.w);
        }
        __half2 z2 = __floats2half2_rn(0.f, 0.f);
        for (int i = 1500 + tid; i < 1652; i += 128)
            reinterpret_cast<__half2*>(xs)[i] = z2;
        const uint4* w4 = reinterpret_cast<const uint4*>(g_Wch);
        uint4* ws4 = reinterpret_cast<uint4*>(ws);
        for (int i = tid; i < 480; i += 128) ws4[i] = w4[i];
    }
    __syncthreads();

    float acc[2][5][4];
#pragma unroll
    for (int mi = 0; mi < 2; mi++)
#pragma unroll
        for (int nt = 0; nt < 5; nt++)
#pragma unroll
            for (int c = 0; c < 4; c++) acc[mi][nt][c] = 0.f;

    const int pbase = warp * 40;
#pragma unroll
    for (int k16 = 0; k16 < 7; k16++) {
        const int k0 = k16 * 16;
        uint32_t a[2][4];
#pragma unroll
        for (int mi = 0; mi < 2; mi++) {
            const int c = mi*16 + gID;
            a[mi][0] = *reinterpret_cast<const uint32_t*>(ws + c*WCP     + k0 + 2*tig);
            a[mi][1] = *reinterpret_cast<const uint32_t*>(ws + (c+8)*WCP + k0 + 2*tig);
            a[mi][2] = *reinterpret_cast<const uint32_t*>(ws + c*WCP     + k0 + 8 + 2*tig);
            a[mi][3] = *reinterpret_cast<const uint32_t*>(ws + (c+8)*WCP + k0 + 8 + 2*tig);
        }
#pragma unroll
        for (int nt = 0; nt < 5; nt++) {
            const int p = pbase + nt*8 + gID;
            uint32_t b0 = *reinterpret_cast<const uint32_t*>(xs + 20*p + k0 + 2*tig);
            uint32_t b1 = *reinterpret_cast<const uint32_t*>(xs + 20*p + k0 + 8 + 2*tig);
            mma_f16(acc[0][nt], a[0], b0, b1);
            mma_f16(acc[1][nt], a[1], b0, b1);
        }
    }

    float bc[2][2];
#pragma unroll
    for (int mi = 0; mi < 2; mi++) {
        bc[mi][0] = cb[mi*16 + gID];
        bc[mi][1] = cb[mi*16 + gID + 8];
    }
    __syncthreads();
    __half* sout = sbuf;                   // 4672 fp16 [c][p]
#pragma unroll
    for (int mi = 0; mi < 2; mi++)
#pragma unroll
        for (int nt = 0; nt < 5; nt++) {
            const int c0 = mi*16 + gID, c1 = c0 + 8;
            const int p0 = pbase + nt*8 + 2*tig;
            if (p0 < REDc) {
                bool two = (p0 + 1 < REDc);
                float v00 = fmaxf(acc[mi][nt][0] + bc[mi][0], 0.f);
                float v01 = two ? fmaxf(acc[mi][nt][1] + bc[mi][0], 0.f) : 0.f;
                float v10 = fmaxf(acc[mi][nt][2] + bc[mi][1], 0.f);
                float v11 = two ? fmaxf(acc[mi][nt][3] + bc[mi][1], 0.f) : 0.f;
                if (two) {
                    *reinterpret_cast<__half2*>(sout + c0*REDc + p0) = __floats2half2_rn(v00, v01);
                    *reinterpret_cast<__half2*>(sout + c1*REDc + p0) = __floats2half2_rn(v10, v11);
                } else {
                    sout[c0*REDc + p0] = __float2half_rn(v00);
                    sout[c1*REDc + p0] = __float2half_rn(v10);
                }
            }
        }
    __syncthreads();
    uint4* o4 = reinterpret_cast<uint4*>(g_h0 + (size_t)n * FINc);
    const uint4* so4 = reinterpret_cast<const uint4*>(sout);
    for (int i = tid; i < 584; i += 128) o4[i] = so4[i];
}

// ---------------- layer1 via mma.sync fp16 (m16n8k16) ----------------
__global__ void __launch_bounds__(256, 2) k_layer1_hf(
    const float* __restrict__ bias,
    const float* __restrict__ gam, const float* __restrict__ bet,
    const float* __restrict__ mean, const float* __restrict__ var)
{
    extern __shared__ float smf[];
    const uint32_t sb = smem_u32(smf);
    const int tid  = threadIdx.x;
    const int b    = blockIdx.x;                 // graph pair
    const int warp = tid >> 5, lane = tid & 31;
    const int wm   = warp >> 1, wn = warp & 1;   // 4 x 2 warp grid
    const int gID  = lane >> 2, tig = lane & 3;

    const __half* Ap = g_h0 + (size_t)b * 128 * FINc;
    const int lr = tid >> 1;
    const int lc = (tid & 1) * 16;

    auto issue = [&](int i) {
        const int s = i & 1;
        const int k0 = i * 32;
        const uint32_t stb = sb + (uint32_t)s * 20480u;
#pragma unroll
        for (int q = 0; q < 2; q++) {
            int c = lc + q * 8;
            uint32_t o = (uint32_t)(lr * 80 + c * 2);
            cp16(stb + o,          Ap   + (size_t)lr * FINc + k0 + c);
            cp16(stb + 10240u + o, g_Wt + (size_t)lr * FINc + k0 + c);
        }
    };

    float acc[2][8][4];
#pragma unroll
    for (int mi = 0; mi < 2; mi++)
#pragma unroll
        for (int j = 0; j < 8; j++)
#pragma unroll
            for (int c = 0; c < 4; c++) acc[mi][j][c] = 0.f;

    issue(0); CP_COMMIT();
    issue(1); CP_COMMIT();

    for (int i = 0; i < TILES; i++) {
        CP_WAIT1();
        __syncthreads();
        const __half* As = reinterpret_cast<const __half*>(
            reinterpret_cast<const char*>(smf) + (i & 1) * 20480);
        const __half* Bs = As + 5120;
#pragma unroll
        for (int kk = 0; kk < 2; kk++) {
            const int k0 = kk * 16;
            uint32_t a[2][4];
#pragma unroll
            for (int mi = 0; mi < 2; mi++) {
                int row = wm*32 + mi*16 + gID;
                a[mi][0] = *reinterpret_cast<const uint32_t*>(As + row*40     + k0 + 2*tig);
                a[mi][1] = *reinterpret_cast<const uint32_t*>(As + (row+8)*40 + k0 + 2*tig);
                a[mi][2] = *reinterpret_cast<const uint32_t*>(As + row*40     + k0 + 8 + 2*tig);
                a[mi][3] = *reinterpret_cast<const uint32_t*>(As + (row+8)*40 + k0 + 8 + 2*tig);
            }
#pragma unroll
            for (int j = 0; j < 8; j++) {
                int n = wn*64 + j*8 + gID;
                uint32_t b0 = *reinterpret_cast<const uint32_t*>(Bs + n*40 + k0 + 2*tig);
                uint32_t b1 = *reinterpret_cast<const uint32_t*>(Bs + n*40 + k0 + 8 + 2*tig);
                mma_f16(acc[0][j], a[0], b0, b1);
                mma_f16(acc[1][j], a[1], b0, b1);
            }
        }
        __syncthreads();
        if (i + 2 < TILES) issue(i + 2);
        CP_COMMIT();
    }

    __syncthreads();
    float* Zs = smf;                               // 128 x 130
    float* Ag = smf + 16640;                       // 2 x (64 x 65)
#pragma unroll
    for (int mi = 0; mi < 2; mi++)
#pragma unroll
        for (int j = 0; j < 8; j++) {
            int row = wm*32 + mi*16 + gID;
            int col = wn*64 + j*8 + 2*tig;
            *reinterpret_cast<float2*>(Zs + row*130 + col) =
                make_float2(acc[mi][j][0], acc[mi][j][1]);
            *reinterpret_cast<float2*>(Zs + (row+8)*130 + col) =
                make_float2(acc[mi][j][2], acc[mi][j][3]);
        }
    {
        const float* gA = g_A + (size_t)(2*b) * 4096;
        for (int i2 = tid; i2 < 8192; i2 += 256) {
            int gg = i2 >> 12, rr = (i2 >> 6) & 63, cc = i2 & 63;
            Ag[gg*4160 + rr*65 + cc] = gA[(size_t)gg*4096 + rr*64 + cc];
        }
    }
    __syncthreads();

    {
        const int gg = tid >> 7;
        const int t  = tid & 127;
        const int tx = t & 15;
        const int ty = t >> 4;
        float ac[8][8];
#pragma unroll
        for (int r = 0; r < 8; r++)
#pragma unroll
            for (int j = 0; j < 8; j++) ac[r][j] = 0.f;

        const float* Agg = Ag + gg * 4160;
        const float* Zg  = Zs + gg * 64 * 130;
#pragma unroll 4
        for (int k = 0; k < 64; k++) {
            float a[8], z[8];
#pragma unroll
            for (int r = 0; r < 8; r++) a[r] = Agg[(ty*8 + r)*65 + k];
#pragma unroll
            for (int j = 0; j < 8; j++) z[j] = Zg[k*130 + tx*8 + j];
#pragma unroll
            for (int r = 0; r < 8; r++)
#pragma unroll
                for (int j = 0; j < 8; j++)
                    ac[r][j] = fmaf(a[r], z[j], ac[r][j]);
        }
        float sc[8], sh[8];
#pragma unroll
        for (int j = 0; j < 8; j++) {
            int col = tx*8 + j;
            float s = gam[col] * rsqrtf(var[col] + EPSf);
            sc[j] = s;
            sh[j] = (bias[col] - mean[col]) * s + bet[col];
        }
#pragma unroll
        for (int r = 0; r < 8; r++) {
            float v[8];
#pragma unroll
            for (int j = 0; j < 8; j++)
                v[j] = fmaxf(fmaf(ac[r][j], sc[j], sh[j]), 0.f);
            float* dst = g_h1 + (size_t)(b*128 + gg*64 + ty*8 + r) * HIDc + tx*8;
            *reinterpret_cast<float4*>(dst)     = make_float4(v[0], v[1], v[2], v[3]);
            *reinterpret_cast<float4*>(dst + 4) = make_float4(v[4], v[5], v[6], v[7]);
        }
    }
}

// ---------------- fused layers 2+3 + pool + FC + log_softmax (fp32) ----------------
// CTA = 1 graph, 256 threads. smem regions (floats):
//  As 0..2304 | Bs 2304..6528 | Ag 6528..10688 | Zs 10688..19136 | H2s 19136..27584
__global__ void __launch_bounds__(256) k_layer23(
    const float* __restrict__ H1, const float* __restrict__ W2,
    const float* __restrict__ b2,
    const float* __restrict__ g2, const float* __restrict__ be2,
    const float* __restrict__ m2, const float* __restrict__ v2,
    const float* __restrict__ W3,
    const float* __restrict__ b3,
    const float* __restrict__ g3, const float* __restrict__ be3,
    const float* __restrict__ m3, const float* __restrict__ v3,
    const float* __restrict__ fcw, const float* __restrict__ fcb,
    float* __restrict__ out)
{
    extern __shared__ float sm[];
    float* As  = sm;             // 64 x 36
    float* Bs  = sm + 2304;      // 32 x 132 (also 32 x 68 for layer3)
    float* Ag  = sm + 6528;      // 64 x 65
    float* Zs  = sm + 10688;     // 64 x 132 (also 64 x 68)
    float* H2s = sm + 19136;     // 64 x 132 (also Ys 64 x 64)

    const int tid = threadIdx.x;
    const int tx  = tid & 15;
    const int ty  = tid >> 4;
    const int g   = blockIdx.x;

    // load A_g once
    for (int i = tid; i < 4096; i += 256)
        Ag[(i >> 6)*65 + (i & 63)] = g_A[(size_t)g*4096 + i];

    const float* Hg = H1 + (size_t)g * 64 * HIDc;
    const int lr = tid >> 2;
    const int lc = (tid & 3) * 8;

    // ---- phase 1: Z2 = H1_g @ W2 (K=128, COUT=128, TN=8) ----
    float acc[4][8];
#pragma unroll
    for (int r = 0; r < 4; r++)
#pragma unroll
        for (int j = 0; j < 8; j++) acc[r][j] = 0.f;

    for (int k0 = 0; k0 < 128; k0 += 32) {
        __syncthreads();
        {
            const float* hp = Hg + (size_t)lr * HIDc + k0 + lc;
            *reinterpret_cast<float4*>(As + lr*36 + lc)     = *reinterpret_cast<const float4*>(hp);
            *reinterpret_cast<float4*>(As + lr*36 + lc + 4) = *reinterpret_cast<const float4*>(hp + 4);
        }
#pragma unroll
        for (int q = 0; q < 4; q++) {
            int idx = tid + q*256;
            int rr  = idx >> 5;
            int cc  = (idx & 31) * 4;
            *reinterpret_cast<float4*>(Bs + rr*132 + cc) =
                *reinterpret_cast<const float4*>(W2 + (size_t)(k0 + rr)*128 + cc);
        }
        __syncthreads();
#pragma unroll 8
        for (int kk = 0; kk < 32; kk++) {
            float a[4];
#pragma unroll
            for (int r = 0; r < 4; r++) a[r] = As[(ty*4 + r)*36 + kk];
            float bb[8];
            *reinterpret_cast<float4*>(bb)     = *reinterpret_cast<const float4*>(Bs + kk*132 + tx*8);
            *reinterpret_cast<float4*>(bb + 4) = *reinterpret_cast<const float4*>(Bs + kk*132 + tx*8 + 4);
#pragma unroll
            for (int r = 0; r < 4; r++)
#pragma unroll
                for (int j = 0; j < 8; j++)
                    acc[r][j] = fmaf(a[r], bb[j], acc[r][j]);
        }
    }
    __syncthreads();
#pragma unroll
    for (int r = 0; r < 4; r++) {
        *reinterpret_cast<float4*>(Zs + (ty*4 + r)*132 + tx*8)     = *reinterpret_cast<float4*>(&acc[r][0]);
        *reinterpret_cast<float4*>(Zs + (ty*4 + r)*132 + tx*8 + 4) = *reinterpret_cast<float4*>(&acc[r][4]);
    }
    __syncthreads();

    // ---- phase 2: H2 = relu(BN2(A@Z2 + b2)) -> H2s ----
#pragma unroll
    for (int r = 0; r < 4; r++)
#pragma unroll
        for (int j = 0; j < 8; j++) acc[r][j] = 0.f;
#pragma unroll 4
    for (int k = 0; k < 64; k++) {
        float a[4];
#pragma unroll
        for (int r = 0; r < 4; r++) a[r] = Ag[(ty*4 + r)*65 + k];
        float zz[8];
        *reinterpret_cast<float4*>(zz)     = *reinterpret_cast<const float4*>(Zs + k*132 + tx*8);
        *reinterpret_cast<float4*>(zz + 4) = *reinterpret_cast<const float4*>(Zs + k*132 + tx*8 + 4);
#pragma unroll
        for (int r = 0; r < 4; r++)
#pragma unroll
            for (int j = 0; j < 8; j++)
                acc[r][j] = fmaf(a[r], zz[j], acc[r][j]);
    }
    {
        float sc[8], sh[8];
#pragma unroll
        for (int j = 0; j < 8; j++) {
            int col = tx*8 + j;
            float s = g2[col] * rsqrtf(v2[col] + EPSf);
            sc[j] = s;
            sh[j] = (b2[col] - m2[col]) * s + be2[col];
        }
#pragma unroll
        for (int r = 0; r < 4; r++)
#pragma unroll
            for (int j = 0; j < 8; j++)
                acc[r][j] = fmaxf(fmaf(acc[r][j], sc[j], sh[j]), 0.f);
#pragma unroll
        for (int r = 0; r < 4; r++) {
            *reinterpret_cast<float4*>(H2s + (ty*4 + r)*132 + tx*8)     = *reinterpret_cast<float4*>(&acc[r][0]);
            *reinterpret_cast<float4*>(H2s + (ty*4 + r)*132 + tx*8 + 4) = *reinterpret_cast<float4*>(&acc[r][4]);
        }
    }

    // ---- phase 3: Z3 = H2 @ W3 (K=128, COUT=64, TN=4); A from H2s directly ----
    float ac3[4][4];
#pragma unroll
    for (int r = 0; r < 4; r++)
#pragma unroll
        for (int j = 0; j < 4; j++) ac3[r][j] = 0.f;

    for (int k0 = 0; k0 < 128; k0 += 32) {
        __syncthreads();
#pragma unroll
        for (int q = 0; q < 2; q++) {
            int idx = tid + q*256;
            int rr  = idx >> 4;
            int cc  = (idx & 15) * 4;
            *reinterpret_cast<float4*>(Bs + rr*68 + cc) =
                *reinterpret_cast<const float4*>(W3 + (size_t)(k0 + rr)*64 + cc);
        }
        __syncthreads();
#pragma unroll 8
        for (int kk = 0; kk < 32; kk++) {
            float a[4];
#pragma unroll
            for (int r = 0; r < 4; r++) a[r] = H2s[(ty*4 + r)*132 + k0 + kk];
            float bb[4];
            *reinterpret_cast<float4*>(bb) = *reinterpret_cast<const float4*>(Bs + kk*68 + tx*4);
#pragma unroll
            for (int r = 0; r < 4; r++)
#pragma unroll
                for (int j = 0; j < 4; j++)
                    ac3[r][j] = fmaf(a[r], bb[j], ac3[r][j]);
        }
    }
    __syncthreads();
#pragma unroll
    for (int r = 0; r < 4; r++)
        *reinterpret_cast<float4*>(Zs + (ty*4 + r)*68 + tx*4) = *reinterpret_cast<float4*>(&ac3[r][0]);
    __syncthreads();

    // ---- phase 4: Y3 = relu(BN3(A@Z3 + b3)) -> Ys (H2s region) ----
#pragma unroll
    for (int r = 0; r < 4; r++)
#pragma unroll
        for (int j = 0; j < 4; j++) ac3[r][j] = 0.f;
#pragma unroll 4
    for (int k = 0; k < 64; k++) {
        float a[4];
#pragma unroll
        for (int r = 0; r < 4; r++) a[r] = Ag[(ty*4 + r)*65 + k];
        float zz[4];
        *reinterpret_cast<float4*>(zz) = *reinterpret_cast<const float4*>(Zs + k*68 + tx*4);
#pragma unroll
        for (int r = 0; r < 4; r++)
#pragma unroll
            for (int j = 0; j < 4; j++)
                ac3[r][j] = fmaf(a[r], zz[j], ac3[r][j]);
    }
    float* Ys = H2s;                 // 64 x 64
    {
        float sc[4], sh[4];
#pragma unroll
        for (int j = 0; j < 4; j++) {
            int col = tx*4 + j;
            float s = g3[col] * rsqrtf(v3[col] + EPSf);
            sc[j] = s;
            sh[j] = (b3[col] - m3[col]) * s + be3[col];
        }
#pragma unroll
        for (int r = 0; r < 4; r++)
#pragma unroll
            for (int j = 0; j < 4; j++)
                Ys[(ty*4 + r)*64 + tx*4 + j] = fmaxf(fmaf(ac3[r][j], sc[j], sh[j]), 0.f);
    }
    __syncthreads();

    // ---- pool + FC + log_softmax ----
    float* pooled = As;
    if (tid < 64) {
        float s = 0.f;
#pragma unroll 8
        for (int i = 0; i < 64; i++) s += Ys[i*64 + tid];
        pooled[tid] = s * (1.0f / 64.0f);
    }
    __syncthreads();
    if (tid < 2) {
        float l = fcb[tid];
#pragma unroll 8
        for (int j = 0; j < 64; j++) l = fmaf(pooled[j], fcw[j*2 + tid], l);
        pooled[64 + tid] = l;
    }
    __syncthreads();
    if (tid == 0) {
        float l0 = pooled[64], l1 = pooled[65];
        float m  = fmaxf(l0, l1);
        float lse = m + logf(expf(l0 - m) + expf(l1 - m));
        out[g*2 + 0] = l0 - lse;
        out[g*2 + 1] = l1 - lse;
    }
}

// ---------------- host launcher ----------------
extern "C" void kernel_launch(void* const* d_in, const int* in_sizes, int n_in,
                              void* d_out, int out_size) {
    const float* x   = (const float*)d_in[0];
    const int*   ei  = (const int*)  d_in[1];
    const float* ea  = (const float*)d_in[2];
    const float* cw  = (const float*)d_in[4];
    const float* cb  = (const float*)d_in[5];
    const float* W1  = (const float*)d_in[6];
    const float* b1  = (const float*)d_in[7];
    const float* W2  = (const float*)d_in[8];
    const float* b2  = (const float*)d_in[9];
    const float* W3  = (const float*)d_in[10];
    const float* b3  = (const float*)d_in[11];
    const float* g1  = (const float*)d_in[12];
    const float* be1 = (const float*)d_in[13];
    const float* m1  = (const float*)d_in[14];
    const float* v1  = (const float*)d_in[15];
    const float* g2  = (const float*)d_in[16];
    const float* be2 = (const float*)d_in[17];
    const float* m2  = (const float*)d_in[18];
    const float* v2  = (const float*)d_in[19];
    const float* g3  = (const float*)d_in[20];
    const float* be3 = (const float*)d_in[21];
    const float* m3  = (const float*)d_in[22];
    const float* v3  = (const float*)d_in[23];
    const float* fcw = (const float*)d_in[24];
    const float* fcb = (const float*)d_in[25];
    float* out = (float*)d_out;

    const int* srcp = ei;
    const int* dstp = ei + Ec;

    float *ph1;
    cudaGetSymbolAddress((void**)&ph1, g_h1);

    k_buildA<<<NG, 256>>>(srcp, dstp, ea);
    {
        dim3 tb(32, 8);
        dim3 gb(FINc/32, HIDc/32);
        k_wt<<<gb, tb>>>(W1);
    }
    k_wc<<<(32*WCP + 255)/256, 256>>>(cw);
    k_conv_tc<<<Nn, 128>>>(x, cb);

    // layer 1 on tensor cores (mma.sync fp16)
    const int smemL1 = (128*130 + 2*64*65) * 4;   // 99840 B
    cudaFuncSetAttribute((const void*)k_layer1_hf,
                         cudaFuncAttributeMaxDynamicSharedMemorySize, smemL1);
    k_layer1_hf<<<NG/2, 256, smemL1>>>(b1, g1, be1, m1, v1);

    // fused layers 2+3 + head
    const int smemL23 = 27584 * 4;   // 110336 B
    cudaFuncSetAttribute((const void*)k_layer23,
                         cudaFuncAttributeMaxDynamicSharedMemorySize, smemL23);
    k_layer23<<<NG, 256, smemL23>>>(ph1, W2, b2, g2, be2, m2, v2,
                                    W3, b3, g3, be3, m3, v3, fcw, fcb, out);
}

// round 10
// speedup vs baseline: 1.8048x; 1.0833x over previous
#include <cuda_runtime.h>
#include <cuda_fp16.h>
#include <math.h>
#include <stdint.h>

// ---------------- problem constants ----------------
#define Nn      32768
#define Ll      3000
#define PERG    64
#define NG      512          // Nn / PERG
#define DEGc    16
#define Ec      (Nn*DEGc)    // 524288
#define HIDc    128
#define OUT3c   64
#define REDc    146
#define FINc    4672         // 32*146
#define EPSf    1e-5f
#define TILES   146          // FINc / 32
#define WCP     120          // conv weight pitch (halves)

// ---------------- device scratch (static, no allocs) ----------------
__device__ float g_A[NG*64*64];                 // 8 MB
__device__ __half g_h0[(size_t)Nn * FINc];      // 306 MB (fp16 conv output)
__device__ __half g_h1[(size_t)Nn * HIDc];      // 8 MB (fp16 layer1 output)
__device__ __half g_Wt[(size_t)HIDc * FINc];    // 1.2 MB: W1^T, fp16
__device__ __half g_Wch[32*WCP];                // conv weights fp16, pitch 120
__device__ __half g_W2t[HIDc*HIDc];             // W2^T [n][k] fp16
__device__ __half g_W3t[OUT3c*HIDc];            // W3^T [n][k] fp16

// ---------------- helpers ----------------
__device__ __forceinline__ uint32_t smem_u32(const void* p) {
    uint32_t a;
    asm("{ .reg .u64 t; cvta.to.shared.u64 t, %1; cvt.u32.u64 %0, t; }" : "=r"(a) : "l"(p));
    return a;
}
__device__ __forceinline__ void mma_f16(float* d, const uint32_t* a, uint32_t b0, uint32_t b1) {
    asm volatile(
        "mma.sync.aligned.m16n8k16.row.col.f32.f16.f16.f32 "
        "{%0,%1,%2,%3}, {%4,%5,%6,%7}, {%8,%9}, {%0,%1,%2,%3};"
        : "+f"(d[0]), "+f"(d[1]), "+f"(d[2]), "+f"(d[3])
        : "r"(a[0]), "r"(a[1]), "r"(a[2]), "r"(a[3]), "r"(b0), "r"(b1));
}
__device__ __forceinline__ void cp16(uint32_t dst, const void* src) {
    asm volatile("cp.async.cg.shared.global [%0], [%1], 16;" :: "r"(dst), "l"(src));
}
#define CP_COMMIT() asm volatile("cp.async.commit_group;" ::: "memory")
#define CP_WAIT1()  asm volatile("cp.async.wait_group 1;" ::: "memory")
__device__ __forceinline__ uint32_t h2u(__half2 h) {
    return *reinterpret_cast<uint32_t*>(&h);
}

// ---------------- per-graph aggregation matrix (deg computed locally) ----------------
__global__ void __launch_bounds__(256) k_buildA(const int* __restrict__ src,
                                                const int* __restrict__ dst,
                                                const float* __restrict__ w) {
    __shared__ float sA[64*64];
    __shared__ float sdeg[64];
    const int g = blockIdx.x, tid = threadIdx.x;
    for (int i = tid; i < 4096; i += 256) sA[i] = 0.f;
    if (tid < 64) sdeg[tid] = 1.0f;
    __syncthreads();
    const int base = g * (PERG * DEGc);
    for (int e = tid; e < PERG*DEGc; e += 256)
        atomicAdd(&sdeg[dst[base + e] - g*64], w[base + e]);
    __syncthreads();
    if (tid < 64) sdeg[tid] = rsqrtf(sdeg[tid]);
    __syncthreads();
    for (int e = tid; e < PERG*DEGc; e += 256) {
        int s = src[base + e] - g*64;
        int d = dst[base + e] - g*64;
        atomicAdd(&sA[d*64 + s], sdeg[s] * w[base + e] * sdeg[d]);
    }
    __syncthreads();
    if (tid < 64) { float di = sdeg[tid]; sA[tid*64 + tid] += di*di; }
    __syncthreads();
    for (int i = tid; i < 4096; i += 256) g_A[g*4096 + i] = sA[i];
}

// ---------------- W1 transpose + fp16 round ----------------
__global__ void k_wt(const float* __restrict__ W) {
    __shared__ float t[32][33];
    int k0 = blockIdx.x * 32, n0 = blockIdx.y * 32;
    int tx = threadIdx.x, ty = threadIdx.y;           // 32 x 8
    for (int r = 0; r < 32; r += 8)
        t[ty + r][tx] = W[(size_t)(k0 + ty + r) * HIDc + n0 + tx];
    __syncthreads();
    for (int r = 0; r < 32; r += 8)
        g_Wt[(size_t)(n0 + ty + r) * FINc + k0 + tx] = __float2half_rn(t[tx][ty + r]);
}

// ---------------- small weight prep: conv weights + W2^T + W3^T ----------------
__global__ void k_wprep(const float* __restrict__ cw,
                        const float* __restrict__ W2,
                        const float* __restrict__ W3) {
    int i = blockIdx.x * blockDim.x + threadIdx.x;
    if (i < 32*WCP) {
        int c = i / WCP, t = i % WCP;
        g_Wch[i] = __float2half_rn((t < 100) ? cw[c*100 + t] : 0.f);
    }
    int j = i - 32*WCP;
    if (j >= 0 && j < HIDc*HIDc) {
        int n = j >> 7, k = j & 127;
        g_W2t[j] = __float2half_rn(W2[k*HIDc + n]);
    }
    int l = j - HIDc*HIDc;
    if (l >= 0 && l < OUT3c*HIDc) {
        int n = l >> 7, k = l & 127;
        g_W3t[l] = __float2half_rn(W3[k*OUT3c + n]);
    }
}

// ---------------- Conv1d via mma.sync fp16 (m16n8k16), fp16 output ----------------
__global__ void __launch_bounds__(128) k_conv_tc(const float* __restrict__ x,
                                                 const float* __restrict__ cb) {
    __shared__ __half sbuf[3304 + 32*WCP];
    __half* xs = sbuf;
    __half* ws = sbuf + 3304;
    const int n    = blockIdx.x;
    const int tid  = threadIdx.x;
    const int warp = tid >> 5, lane = tid & 31;
    const int gID  = lane >> 2, tig = lane & 3;

    {
        const float4* x4 = reinterpret_cast<const float4*>(x + (size_t)n * Ll);
        for (int i = tid; i < 750; i += 128) {
            float4 v = x4[i];
            __half2* d = reinterpret_cast<__half2*>(xs + i*4);
            d[0] = __floats2half2_rn(v.x, v.y);
            d[1] = __floats2half2_rn(v.z, v.w);
        }
        __half2 z2 = __floats2half2_rn(0.f, 0.f);
        for (int i = 1500 + tid; i < 1652; i += 128)
            reinterpret_cast<__half2*>(xs)[i] = z2;
        const uint4* w4 = reinterpret_cast<const uint4*>(g_Wch);
        uint4* ws4 = reinterpret_cast<uint4*>(ws);
        for (int i = tid; i < 480; i += 128) ws4[i] = w4[i];
    }
    __syncthreads();

    float acc[2][5][4];
#pragma unroll
    for (int mi = 0; mi < 2; mi++)
#pragma unroll
        for (int nt = 0; nt < 5; nt++)
#pragma unroll
            for (int c = 0; c < 4; c++) acc[mi][nt][c] = 0.f;

    const int pbase = warp * 40;
#pragma unroll
    for (int k16 = 0; k16 < 7; k16++) {
        const int k0 = k16 * 16;
        uint32_t a[2][4];
#pragma unroll
        for (int mi = 0; mi < 2; mi++) {
            const int c = mi*16 + gID;
            a[mi][0] = *reinterpret_cast<const uint32_t*>(ws + c*WCP     + k0 + 2*tig);
            a[mi][1] = *reinterpret_cast<const uint32_t*>(ws + (c+8)*WCP + k0 + 2*tig);
            a[mi][2] = *reinterpret_cast<const uint32_t*>(ws + c*WCP     + k0 + 8 + 2*tig);
            a[mi][3] = *reinterpret_cast<const uint32_t*>(ws + (c+8)*WCP + k0 + 8 + 2*tig);
        }
#pragma unroll
        for (int nt = 0; nt < 5; nt++) {
            const int p = pbase + nt*8 + gID;
            uint32_t b0 = *reinterpret_cast<const uint32_t*>(xs + 20*p + k0 + 2*tig);
            uint32_t b1 = *reinterpret_cast<const uint32_t*>(xs + 20*p + k0 + 8 + 2*tig);
            mma_f16(acc[0][nt], a[0], b0, b1);
            mma_f16(acc[1][nt], a[1], b0, b1);
        }
    }

    float bc[2][2];
#pragma unroll
    for (int mi = 0; mi < 2; mi++) {
        bc[mi][0] = cb[mi*16 + gID];
        bc[mi][1] = cb[mi*16 + gID + 8];
    }
    __syncthreads();
    __half* sout = sbuf;
#pragma unroll
    for (int mi = 0; mi < 2; mi++)
#pragma unroll
        for (int nt = 0; nt < 5; nt++) {
            const int c0 = mi*16 + gID, c1 = c0 + 8;
            const int p0 = pbase + nt*8 + 2*tig;
            if (p0 < REDc) {
                bool two = (p0 + 1 < REDc);
                float v00 = fmaxf(acc[mi][nt][0] + bc[mi][0], 0.f);
                float v01 = two ? fmaxf(acc[mi][nt][1] + bc[mi][0], 0.f) : 0.f;
                float v10 = fmaxf(acc[mi][nt][2] + bc[mi][1], 0.f);
                float v11 = two ? fmaxf(acc[mi][nt][3] + bc[mi][1], 0.f) : 0.f;
                if (two) {
                    *reinterpret_cast<__half2*>(sout + c0*REDc + p0) = __floats2half2_rn(v00, v01);
                    *reinterpret_cast<__half2*>(sout + c1*REDc + p0) = __floats2half2_rn(v10, v11);
                } else {
                    sout[c0*REDc + p0] = __float2half_rn(v00);
                    sout[c1*REDc + p0] = __float2half_rn(v10);
                }
            }
        }
    __syncthreads();
    uint4* o4 = reinterpret_cast<uint4*>(g_h0 + (size_t)n * FINc);
    const uint4* so4 = reinterpret_cast<const uint4*>(sout);
    for (int i = tid; i < 584; i += 128) o4[i] = so4[i];
}

// ---------------- layer1 via mma.sync fp16 (m16n8k16), fp16 output ----------------
__global__ void __launch_bounds__(256, 2) k_layer1_hf(
    const float* __restrict__ bias,
    const float* __restrict__ gam, const float* __restrict__ bet,
    const float* __restrict__ mean, const float* __restrict__ var)
{
    extern __shared__ float smf[];
    const uint32_t sb = smem_u32(smf);
    const int tid  = threadIdx.x;
    const int b    = blockIdx.x;
    const int warp = tid >> 5, lane = tid & 31;
    const int wm   = warp >> 1, wn = warp & 1;
    const int gID  = lane >> 2, tig = lane & 3;

    const __half* Ap = g_h0 + (size_t)b * 128 * FINc;
    const int lr = tid >> 1;
    const int lc = (tid & 1) * 16;

    auto issue = [&](int i) {
        const int s = i & 1;
        const int k0 = i * 32;
        const uint32_t stb = sb + (uint32_t)s * 20480u;
#pragma unroll
        for (int q = 0; q < 2; q++) {
            int c = lc + q * 8;
            uint32_t o = (uint32_t)(lr * 80 + c * 2);
            cp16(stb + o,          Ap   + (size_t)lr * FINc + k0 + c);
            cp16(stb + 10240u + o, g_Wt + (size_t)lr * FINc + k0 + c);
        }
    };

    float acc[2][8][4];
#pragma unroll
    for (int mi = 0; mi < 2; mi++)
#pragma unroll
        for (int j = 0; j < 8; j++)
#pragma unroll
            for (int c = 0; c < 4; c++) acc[mi][j][c] = 0.f;

    issue(0); CP_COMMIT();
    issue(1); CP_COMMIT();

    for (int i = 0; i < TILES; i++) {
        CP_WAIT1();
        __syncthreads();
        const __half* As = reinterpret_cast<const __half*>(
            reinterpret_cast<const char*>(smf) + (i & 1) * 20480);
        const __half* Bs = As + 5120;
#pragma unroll
        for (int kk = 0; kk < 2; kk++) {
            const int k0 = kk * 16;
            uint32_t a[2][4];
#pragma unroll
            for (int mi = 0; mi < 2; mi++) {
                int row = wm*32 + mi*16 + gID;
                a[mi][0] = *reinterpret_cast<const uint32_t*>(As + row*40     + k0 + 2*tig);
                a[mi][1] = *reinterpret_cast<const uint32_t*>(As + (row+8)*40 + k0 + 2*tig);
                a[mi][2] = *reinterpret_cast<const uint32_t*>(As + row*40     + k0 + 8 + 2*tig);
                a[mi][3] = *reinterpret_cast<const uint32_t*>(As + (row+8)*40 + k0 + 8 + 2*tig);
            }
#pragma unroll
            for (int j = 0; j < 8; j++) {
                int n = wn*64 + j*8 + gID;
                uint32_t b0 = *reinterpret_cast<const uint32_t*>(Bs + n*40 + k0 + 2*tig);
                uint32_t b1 = *reinterpret_cast<const uint32_t*>(Bs + n*40 + k0 + 8 + 2*tig);
                mma_f16(acc[0][j], a[0], b0, b1);
                mma_f16(acc[1][j], a[1], b0, b1);
            }
        }
        __syncthreads();
        if (i + 2 < TILES) issue(i + 2);
        CP_COMMIT();
    }

    __syncthreads();
    float* Zs = smf;                               // 128 x 130
    float* Ag = smf + 16640;                       // 2 x (64 x 65)
#pragma unroll
    for (int mi = 0; mi < 2; mi++)
#pragma unroll
        for (int j = 0; j < 8; j++) {
            int row = wm*32 + mi*16 + gID;
            int col = wn*64 + j*8 + 2*tig;
            *reinterpret_cast<float2*>(Zs + row*130 + col) =
                make_float2(acc[mi][j][0], acc[mi][j][1]);
            *reinterpret_cast<float2*>(Zs + (row+8)*130 + col) =
                make_float2(acc[mi][j][2], acc[mi][j][3]);
        }
    {
        const float* gA = g_A + (size_t)(2*b) * 4096;
        for (int i2 = tid; i2 < 8192; i2 += 256) {
            int gg = i2 >> 12, rr = (i2 >> 6) & 63, cc = i2 & 63;
            Ag[gg*4160 + rr*65 + cc] = gA[(size_t)gg*4096 + rr*64 + cc];
        }
    }
    __syncthreads();

    {
        const int gg = tid >> 7;
        const int t  = tid & 127;
        const int tx = t & 15;
        const int ty = t >> 4;
        float ac[8][8];
#pragma unroll
        for (int r = 0; r < 8; r++)
#pragma unroll
            for (int j = 0; j < 8; j++) ac[r][j] = 0.f;

        const float* Agg = Ag + gg * 4160;
        const float* Zg  = Zs + gg * 64 * 130;
#pragma unroll 4
        for (int k = 0; k < 64; k++) {
            float a[8], z[8];
#pragma unroll
            for (int r = 0; r < 8; r++) a[r] = Agg[(ty*8 + r)*65 + k];
#pragma unroll
            for (int j = 0; j < 8; j++) z[j] = Zg[k*130 + tx*8 + j];
#pragma unroll
            for (int r = 0; r < 8; r++)
#pragma unroll
                for (int j = 0; j < 8; j++)
                    ac[r][j] = fmaf(a[r], z[j], ac[r][j]);
        }
        float sc[8], sh[8];
#pragma unroll
        for (int j = 0; j < 8; j++) {
            int col = tx*8 + j;
            float s = gam[col] * rsqrtf(var[col] + EPSf);
            sc[j] = s;
            sh[j] = (bias[col] - mean[col]) * s + bet[col];
        }
#pragma unroll
        for (int r = 0; r < 8; r++) {
            float v[8];
#pragma unroll
            for (int j = 0; j < 8; j++)
                v[j] = fmaxf(fmaf(ac[r][j], sc[j], sh[j]), 0.f);
            uint4 pk;
            pk.x = h2u(__floats2half2_rn(v[0], v[1]));
            pk.y = h2u(__floats2half2_rn(v[2], v[3]));
            pk.z = h2u(__floats2half2_rn(v[4], v[5]));
            pk.w = h2u(__floats2half2_rn(v[6], v[7]));
            *reinterpret_cast<uint4*>(g_h1 + (size_t)(b*128 + gg*64 + ty*8 + r)*HIDc + tx*8) = pk;
        }
    }
}

// ---------------- fused layers 2+3 + head; GEMMs on fp16 MMA ----------------
// CTA = 1 graph, 256 threads (8 warps: wm = warp>>2, wn = warp&3).
// smem (floats): Ag 0..4160 | Zs 4160..12608 (64x132 / 64x68) | Hh 12608..16960 (half 64x136)
__global__ void __launch_bounds__(256) k_layer23(
    const float* __restrict__ b2,
    const float* __restrict__ g2, const float* __restrict__ be2,
    const float* __restrict__ m2, const float* __restrict__ v2,
    const float* __restrict__ b3,
    const float* __restrict__ g3, const float* __restrict__ be3,
    const float* __restrict__ m3, const float* __restrict__ v3,
    const float* __restrict__ fcw, const float* __restrict__ fcb,
    float* __restrict__ out)
{
    extern __shared__ float sm[];
    float* Ag = sm;              // 64 x 65
    float* Zs = sm + 4160;       // 64 x 132 fp32 (later 64 x 68)
    __half* Hh = reinterpret_cast<__half*>(sm + 12608);   // 64 x 136 halves

    const int tid = threadIdx.x;
    const int g   = blockIdx.x;
    const int warp = tid >> 5, lane = tid & 31;
    const int wm = warp >> 2, wn = warp & 3;
    const int gID = lane >> 2, tig = lane & 3;
    const int tx = tid & 15, ty = tid >> 4;

    // load A_g and H1 (fp16) into smem
    for (int i = tid; i < 4096; i += 256)
        Ag[(i >> 6)*65 + (i & 63)] = g_A[(size_t)g*4096 + i];
    {
        const uint4* src = reinterpret_cast<const uint4*>(g_h1 + (size_t)g * 64 * HIDc);
        for (int i = tid; i < 1024; i += 256) {
            int row = i >> 4, c8 = i & 15;
            *reinterpret_cast<uint4*>(Hh + row*136 + c8*8) = src[i];
        }
    }
    __syncthreads();

    // ---- phase 1 (MMA): Z2 = H1 @ W2  (M=64, N=128, K=128) ----
    float acc[2][4][4];
#pragma unroll
    for (int mi = 0; mi < 2; mi++)
#pragma unroll
        for (int j = 0; j < 4; j++)
#pragma unroll
            for (int c = 0; c < 4; c++) acc[mi][j][c] = 0.f;
#pragma unroll
    for (int k16 = 0; k16 < 8; k16++) {
        const int k0 = k16 * 16;
        uint32_t a[2][4];
#pragma unroll
        for (int mi = 0; mi < 2; mi++) {
            int row = wm*32 + mi*16 + gID;
            a[mi][0] = *reinterpret_cast<const uint32_t*>(Hh + row*136     + k0 + 2*tig);
            a[mi][1] = *reinterpret_cast<const uint32_t*>(Hh + (row+8)*136 + k0 + 2*tig);
            a[mi][2] = *reinterpret_cast<const uint32_t*>(Hh + row*136     + k0 + 8 + 2*tig);
            a[mi][3] = *reinterpret_cast<const uint32_t*>(Hh + (row+8)*136 + k0 + 8 + 2*tig);
        }
#pragma unroll
        for (int j = 0; j < 4; j++) {
            int n = wn*32 + j*8 + gID;
            uint32_t b0 = __ldg(reinterpret_cast<const uint32_t*>(g_W2t + n*HIDc + k0 + 2*tig));
            uint32_t b1 = __ldg(reinterpret_cast<const uint32_t*>(g_W2t + n*HIDc + k0 + 8 + 2*tig));
            mma_f16(acc[0][j], a[0], b0, b1);
            mma_f16(acc[1][j], a[1], b0, b1);
        }
    }
    __syncthreads();   // Hh reads done (will be overwritten in phase 2)
#pragma unroll
    for (int mi = 0; mi < 2; mi++)
#pragma unroll
        for (int j = 0; j < 4; j++) {
            int row = wm*32 + mi*16 + gID;
            int col = wn*32 + j*8 + 2*tig;
            *reinterpret_cast<float2*>(Zs + row*132 + col) =
                make_float2(acc[mi][j][0], acc[mi][j][1]);
            *reinterpret_cast<float2*>(Zs + (row+8)*132 + col) =
                make_float2(acc[mi][j][2], acc[mi][j][3]);
        }
    __syncthreads();

    // ---- phase 2 (fp32): H2 = relu(BN2(A@Z2 + b2)) -> Hh (fp16) ----
    {
        float ac[4][8];
#pragma unroll
        for (int r = 0; r < 4; r++)
#pragma unroll
            for (int j = 0; j < 8; j++) ac[r][j] = 0.f;
#pragma unroll 4
        for (int k = 0; k < 64; k++) {
            float a[4];
#pragma unroll
            for (int r = 0; r < 4; r++) a[r] = Ag[(ty*4 + r)*65 + k];
            float zz[8];
            *reinterpret_cast<float4*>(zz)     = *reinterpret_cast<const float4*>(Zs + k*132 + tx*8);
            *reinterpret_cast<float4*>(zz + 4) = *reinterpret_cast<const float4*>(Zs + k*132 + tx*8 + 4);
#pragma unroll
            for (int r = 0; r < 4; r++)
#pragma unroll
                for (int j = 0; j < 8; j++)
                    ac[r][j] = fmaf(a[r], zz[j], ac[r][j]);
        }
        float sc[8], sh[8];
#pragma unroll
        for (int j = 0; j < 8; j++) {
            int col = tx*8 + j;
            float s = g2[col] * rsqrtf(v2[col] + EPSf);
            sc[j] = s;
            sh[j] = (b2[col] - m2[col]) * s + be2[col];
        }
#pragma unroll
        for (int r = 0; r < 4; r++) {
            float v[8];
#pragma unroll
            for (int j = 0; j < 8; j++)
                v[j] = fmaxf(fmaf(ac[r][j], sc[j], sh[j]), 0.f);
            __half2* d = reinterpret_cast<__half2*>(Hh + (ty*4 + r)*136 + tx*8);
            d[0] = __floats2half2_rn(v[0], v[1]);
            d[1] = __floats2half2_rn(v[2], v[3]);
            d[2] = __floats2half2_rn(v[4], v[5]);
            d[3] = __floats2half2_rn(v[6], v[7]);
        }
    }
    __syncthreads();

    // ---- phase 3 (MMA): Z3 = H2 @ W3  (M=64, N=64, K=128) ----
    float ac3[2][2][4];
#pragma unroll
    for (int mi = 0; mi < 2; mi++)
#pragma unroll
        for (int j = 0; j < 2; j++)
#pragma unroll
            for (int c = 0; c < 4; c++) ac3[mi][j][c] = 0.f;
#pragma unroll
    for (int k16 = 0; k16 < 8; k16++) {
        const int k0 = k16 * 16;
        uint32_t a[2][4];
#pragma unroll
        for (int mi = 0; mi < 2; mi++) {
            int row = wm*32 + mi*16 + gID;
            a[mi][0] = *reinterpret_cast<const uint32_t*>(Hh + row*136     + k0 + 2*tig);
            a[mi][1] = *reinterpret_cast<const uint32_t*>(Hh + (row+8)*136 + k0 + 2*tig);
            a[mi][2] = *reinterpret_cast<const uint32_t*>(Hh + row*136     + k0 + 8 + 2*tig);
            a[mi][3] = *reinterpret_cast<const uint32_t*>(Hh + (row+8)*136 + k0 + 8 + 2*tig);
        }
#pragma unroll
        for (int j = 0; j < 2; j++) {
            int n = wn*16 + j*8 + gID;
            uint32_t b0 = __ldg(reinterpret_cast<const uint32_t*>(g_W3t + n*HIDc + k0 + 2*tig));
            uint32_t b1 = __ldg(reinterpret_cast<const uint32_t*>(g_W3t + n*HIDc + k0 + 8 + 2*tig));
            mma_f16(ac3[0][j], a[0], b0, b1);
            mma_f16(ac3[1][j], a[1], b0, b1);
        }
    }
    __syncthreads();   // Zs (Z2) reads long done; reuse as 64x68
#pragma unroll
    for (int mi = 0; mi < 2; mi++)
#pragma unroll
        for (int j = 0; j < 2; j++) {
            int row = wm*32 + mi*16 + gID;
            int col = wn*16 + j*8 + 2*tig;
            *reinterpret_cast<float2*>(Zs + row*68 + col) =
                make_float2(ac3[mi][j][0], ac3[mi][j][1]);
            *reinterpret_cast<float2*>(Zs + (row+8)*68 + col) =
                make_float2(ac3[mi][j][2], ac3[mi][j][3]);
        }
    __syncthreads();

    // ---- phase 4 (fp32): Y3 = relu(BN3(A@Z3 + b3)) -> Ys ----
    float* Ys = reinterpret_cast<float*>(Hh);   // 64 x 64 (Hh dead)
    {
        float ac[4][4];
#pragma unroll
        for (int r = 0; r < 4; r++)
#pragma unroll
            for (int j = 0; j < 4; j++) ac[r][j] = 0.f;
#pragma unroll 4
        for (int k = 0; k < 64; k++) {
            float a[4];
#pragma unroll
            for (int r = 0; r < 4; r++) a[r] = Ag[(ty*4 + r)*65 + k];
            float zz[4];
            *reinterpret_cast<float4*>(zz) = *reinterpret_cast<const float4*>(Zs + k*68 + tx*4);
#pragma unroll
            for (int r = 0; r < 4; r++)
#pragma unroll
                for (int j = 0; j < 4; j++)
                    ac[r][j] = fmaf(a[r], zz[j], ac[r][j]);
        }
        float sc[4], sh[4];
#pragma unroll
        for (int j = 0; j < 4; j++) {
            int col = tx*4 + j;
            float s = g3[col] * rsqrtf(v3[col] + EPSf);
            sc[j] = s;
            sh[j] = (b3[col] - m3[col]) * s + be3[col];
        }
        __syncthreads();   // ensure all phase-3 Hh reads done before overwrite
#pragma unroll
        for (int r = 0; r < 4; r++)
#pragma unroll
            for (int j = 0; j < 4; j++)
                Ys[(ty*4 + r)*64 + tx*4 + j] = fmaxf(fmaf(ac[r][j], sc[j], sh[j]), 0.f);
    }
    __syncthreads();

    // ---- pool + FC + log_softmax ----
    float* pooled = Ag;   // Ag dead
    if (tid < 64) {
        float s = 0.f;
#pragma unroll 8
        for (int i = 0; i < 64; i++) s += Ys[i*64 + tid];
        pooled[tid] = s * (1.0f / 64.0f);
    }
    __syncthreads();
    if (tid < 2) {
        float l = fcb[tid];
#pragma unroll 8
        for (int j = 0; j < 64; j++) l = fmaf(pooled[j], fcw[j*2 + tid], l);
        pooled[64 + tid] = l;
    }
    __syncthreads();
    if (tid == 0) {
        float l0 = pooled[64], l1 = pooled[65];
        float m  = fmaxf(l0, l1);
        float lse = m + logf(expf(l0 - m) + expf(l1 - m));
        out[g*2 + 0] = l0 - lse;
        out[g*2 + 1] = l1 - lse;
    }
}

// ---------------- host launcher ----------------
extern "C" void kernel_launch(void* const* d_in, const int* in_sizes, int n_in,
                              void* d_out, int out_size) {
    const float* x   = (const float*)d_in[0];
    const int*   ei  = (const int*)  d_in[1];
    const float* ea  = (const float*)d_in[2];
    const float* cw  = (const float*)d_in[4];
    const float* cb  = (const float*)d_in[5];
    const float* W1  = (const float*)d_in[6];
    const float* b1  = (const float*)d_in[7];
    const float* W2  = (const float*)d_in[8];
    const float* b2  = (const float*)d_in[9];
    const float* W3  = (const float*)d_in[10];
    const float* b3  = (const float*)d_in[11];
    const float* g1  = (const float*)d_in[12];
    const float* be1 = (const float*)d_in[13];
    const float* m1  = (const float*)d_in[14];
    const float* v1  = (const float*)d_in[15];
    const float* g2  = (const float*)d_in[16];
    const float* be2 = (const float*)d_in[17];
    const float* m2  = (const float*)d_in[18];
    const float* v2  = (const float*)d_in[19];
    const float* g3  = (const float*)d_in[20];
    const float* be3 = (const float*)d_in[21];
    const float* m3  = (const float*)d_in[22];
    const float* v3  = (const float*)d_in[23];
    const float* fcw = (const float*)d_in[24];
    const float* fcb = (const float*)d_in[25];
    float* out = (float*)d_out;

    const int* srcp = ei;
    const int* dstp = ei + Ec;

    k_buildA<<<NG, 256>>>(srcp, dstp, ea);
    {
        dim3 tb(32, 8);
        dim3 gb(FINc/32, HIDc/32);
        k_wt<<<gb, tb>>>(W1);
    }
    {
        int tot = 32*WCP + HIDc*HIDc + OUT3c*HIDc;
        k_wprep<<<(tot + 255)/256, 256>>>(cw, W2, W3);
    }
    k_conv_tc<<<Nn, 128>>>(x, cb);

    const int smemL1 = (128*130 + 2*64*65) * 4;   // 99840 B
    cudaFuncSetAttribute((const void*)k_layer1_hf,
                         cudaFuncAttributeMaxDynamicSharedMemorySize, smemL1);
    k_layer1_hf<<<NG/2, 256, smemL1>>>(b1, g1, be1, m1, v1);

    const int smemL23 = 16960 * 4;   // 67840 B
    cudaFuncSetAttribute((const void*)k_layer23,
                         cudaFuncAttributeMaxDynamicSharedMemorySize, smemL23);
    k_layer23<<<NG, 256, smemL23>>>(b2, g2, be2, m2, v2,
                                    b3, g3, be3, m3, v3, fcw, fcb, out);
}